// round 4
// baseline (speedup 1.0000x reference)
#include <cuda_runtime.h>
#include <math.h>
#include <stdint.h>
#include <float.h>

#define B_  2
#define T_  2048
#define HID_ 2048
#define H_  16
#define D_  128
#define BH_ (B_*H_)
#define BT_ (B_*T_)

__device__ float g_Q[(size_t)BH_ * T_ * D_];
__device__ float g_K[(size_t)BH_ * T_ * D_];
__device__ float g_V[(size_t)BH_ * T_ * D_];
__device__ float g_AO[(size_t)BT_ * HID_];
__device__ float g_Abar[BH_ * T_];
__device__ float g_ve[BH_ * D_];

// ---------------- SGEMM NT: C[i,j] = sum_k A[i,k]*W[j,k] ----------------
template<int MODE>
__global__ void __launch_bounds__(256, 2) sgemm_nt(
    const float* __restrict__ A,
    const float* __restrict__ W0, const float* __restrict__ W1, const float* __restrict__ W2,
    float* __restrict__ C)
{
    __shared__ float As[2][8][132];
    __shared__ float Bs[2][8][132];
    const int tid = threadIdx.x;
    const int m0 = blockIdx.y * 128;
    const int n0 = blockIdx.x * 128;

    const float* Bw = (MODE == 1) ? ((blockIdx.z == 0) ? W0 : (blockIdx.z == 1 ? W1 : W2)) : W0;
    const float* Ax = (MODE == 0) ? (const float*)g_AO : A;

    const int lr = tid >> 1;
    const int ls = (tid & 1) * 4;
    const float* Ap = Ax + (size_t)(m0 + lr) * 2048 + ls;
    const float* Bp = Bw + (size_t)(n0 + lr) * 2048 + ls;
    const int tm8 = (tid >> 4) << 3;
    const int tn8 = (tid & 15) << 3;

    float acc[8][8];
#pragma unroll
    for (int i = 0; i < 8; i++)
#pragma unroll
        for (int j = 0; j < 8; j++) acc[i][j] = 0.f;

    float4 a4 = *(const float4*)Ap;
    float4 b4 = *(const float4*)Bp;
    As[0][ls+0][lr]=a4.x; As[0][ls+1][lr]=a4.y; As[0][ls+2][lr]=a4.z; As[0][ls+3][lr]=a4.w;
    Bs[0][ls+0][lr]=b4.x; Bs[0][ls+1][lr]=b4.y; Bs[0][ls+2][lr]=b4.z; Bs[0][ls+3][lr]=b4.w;
    __syncthreads();

    int buf = 0;
    for (int it = 1; it <= 256; ++it) {
        if (it < 256) {
            a4 = *(const float4*)(Ap + it * 8);
            b4 = *(const float4*)(Bp + it * 8);
        }
#pragma unroll
        for (int kk = 0; kk < 8; kk++) {
            float ar[8], br[8];
            *(float4*)&ar[0] = *(const float4*)&As[buf][kk][tm8];
            *(float4*)&ar[4] = *(const float4*)&As[buf][kk][tm8+4];
            *(float4*)&br[0] = *(const float4*)&Bs[buf][kk][tn8];
            *(float4*)&br[4] = *(const float4*)&Bs[buf][kk][tn8+4];
#pragma unroll
            for (int i = 0; i < 8; i++)
#pragma unroll
                for (int j = 0; j < 8; j++)
                    acc[i][j] = fmaf(ar[i], br[j], acc[i][j]);
        }
        buf ^= 1;
        if (it < 256) {
            As[buf][ls+0][lr]=a4.x; As[buf][ls+1][lr]=a4.y; As[buf][ls+2][lr]=a4.z; As[buf][ls+3][lr]=a4.w;
            Bs[buf][ls+0][lr]=b4.x; Bs[buf][ls+1][lr]=b4.y; Bs[buf][ls+2][lr]=b4.z; Bs[buf][ls+3][lr]=b4.w;
        }
        __syncthreads();
    }

    if (MODE == 0) {
#pragma unroll
        for (int i = 0; i < 8; i++) {
            float* cp = C + (size_t)(m0 + tm8 + i) * 2048 + n0 + tn8;
            *(float4*)(cp+0) = make_float4(acc[i][0], acc[i][1], acc[i][2], acc[i][3]);
            *(float4*)(cp+4) = make_float4(acc[i][4], acc[i][5], acc[i][6], acc[i][7]);
        }
    } else {
        float* G = (blockIdx.z == 0) ? g_Q : (blockIdx.z == 1 ? g_K : g_V);
        const int h = blockIdx.x;
#pragma unroll
        for (int i = 0; i < 8; i++) {
            const int r = m0 + tm8 + i;
            const int b = r >> 11;
            const int t = r & 2047;
            float* cp = G + (((size_t)(b * H_ + h) * T_ + t) << 7) + tn8;
            *(float4*)(cp+0) = make_float4(acc[i][0], acc[i][1], acc[i][2], acc[i][3]);
            *(float4*)(cp+4) = make_float4(acc[i][4], acc[i][5], acc[i][6], acc[i][7]);
        }
    }
}

// ---------------- RoPE in place on Q and K ----------------
__global__ void rope_kernel()
{
    const int idx = blockIdx.x * blockDim.x + threadIdx.x;
    const int per = BH_ * T_ * 64;
    float* P = (idx < per) ? g_Q : g_K;
    const int i = (idx < per) ? idx : idx - per;
    const int j = i & 63;
    const int bht = i >> 6;
    const int t = bht & (T_ - 1);
    const float inv = powf(10000.f, -(float)j * (1.f / 64.f));
    float s, c;
    sincosf((float)t * inv, &s, &c);
    float* row = P + (size_t)bht * 128;
    const float x1 = row[j];
    const float x2 = row[j + 64];
    row[j]      = x1 * c - x2 * s;
    row[j + 64] = x2 * c + x1 * s;
}

// ---------------- A_bar: softmax of last query row per (b,h) ----------------
__global__ void __launch_bounds__(256) abar_kernel()
{
    const int bh = blockIdx.x;
    __shared__ float qrow[128];
    __shared__ float sc[2048];
    __shared__ float red[256];
    const int tid = threadIdx.x;

    const float* Qr = g_Q + ((size_t)bh * T_ + (T_ - 1)) * 128;
    if (tid < 128) qrow[tid] = Qr[tid];
    __syncthreads();

    for (int k = tid; k < 2048; k += 256) {
        const float4* kr = (const float4*)(g_K + ((size_t)bh * T_ + k) * 128);
        const float4* qr = (const float4*)qrow;
        float s = 0.f;
#pragma unroll
        for (int i = 0; i < 32; i++) {
            const float4 kv = kr[i], qv = qr[i];
            s = fmaf(kv.x, qv.x, s); s = fmaf(kv.y, qv.y, s);
            s = fmaf(kv.z, qv.z, s); s = fmaf(kv.w, qv.w, s);
        }
        sc[k] = s * 0.08838834764831845f;
    }
    __syncthreads();

    float m = -FLT_MAX;
    for (int k = tid; k < 2048; k += 256) m = fmaxf(m, sc[k]);
    red[tid] = m; __syncthreads();
    for (int o = 128; o > 0; o >>= 1) { if (tid < o) red[tid] = fmaxf(red[tid], red[tid + o]); __syncthreads(); }
    const float gm = red[0];
    __syncthreads();

    float sum = 0.f;
    for (int k = tid; k < 2048; k += 256) { const float p = expf(sc[k] - gm); sc[k] = p; sum += p; }
    red[tid] = sum; __syncthreads();
    for (int o = 128; o > 0; o >>= 1) { if (tid < o) red[tid] += red[tid + o]; __syncthreads(); }
    const float invs = 1.f / red[0];

    for (int k = tid; k < 2048; k += 256) g_Abar[bh * 2048 + k] = sc[k] * invs;
}

// ---------------- CAM prep: prob, PARTITIONABLE threefry2x32 bernoulli, v_e ----------------
// JAX >= 0.4.36 default (jax_threefry_partitionable=True):
//   per element i: (x0,x1) = threefry2x32(key=(0,42), counts=(hi32(i)=0, lo32(i)=i))
//   bits_i = x0 ^ x1
__device__ __forceinline__ uint32_t rotl32(uint32_t x, int r) { return (x << r) | (x >> (32 - r)); }

__global__ void cam_prep_kernel()
{
    __shared__ float prob[32];
    __shared__ float maskv[32];
    const int tid = threadIdx.x;

    if (tid < 32) {
        const float* ab = g_Abar + tid * 2048;
        float sum = 0.f;
        for (int i = 1536; i < 2048; i++) sum += ab[i];
        const float avg = fmaxf(sum * (1.f / 512.f), 1e-6f);
        float p = ab[1535] / avg;
        p = fminf(fmaxf(p, 0.f), 1.f);
        prob[tid] = p;

        // partitionable threefry: x0 = hi32(i) = 0, x1 = lo32(i) = i
        uint32_t x0 = 0u, x1 = (uint32_t)tid;
        const uint32_t k0 = 0u, k1 = 42u, k2 = 0x1BD11BDAu ^ k0 ^ k1;
        x0 += k0; x1 += k1;
#define TF4(a,b,c,d)  x0+=x1; x1=rotl32(x1,a); x1^=x0; \
                      x0+=x1; x1=rotl32(x1,b); x1^=x0; \
                      x0+=x1; x1=rotl32(x1,c); x1^=x0; \
                      x0+=x1; x1=rotl32(x1,d); x1^=x0;
        TF4(13,15,26,6)   x0 += k1; x1 += k2 + 1u;
        TF4(17,29,16,24)  x0 += k2; x1 += k0 + 2u;
        TF4(13,15,26,6)   x0 += k0; x1 += k1 + 3u;
        TF4(17,29,16,24)  x0 += k1; x1 += k2 + 4u;
        TF4(13,15,26,6)   x0 += k2; x1 += k0 + 5u;
#undef TF4
        const uint32_t bits = x0 ^ x1;

        float u = __uint_as_float((bits >> 9) | 0x3f800000u) - 1.0f;
        u = fmaxf(u, 0.f);
        maskv[tid] = (u < p) ? 1.f : 0.f;
    }
    __syncthreads();

    for (int i = tid; i < 32 * 128; i += blockDim.x) {
        const int bh = i >> 7, d = i & 127;
        g_ve[i] = g_V[((size_t)bh * T_ + 1535) * 128 + d] * maskv[bh] * (1.f / 512.f);
    }
}

__global__ void v_update_kernel()
{
    const int idx = blockIdx.x * blockDim.x + threadIdx.x;
    const int bh = idx >> 16;
    const int rest = idx & 65535;
    const int r = rest >> 7;
    const int d = rest & 127;
    g_V[((size_t)bh * T_ + 1536 + r) * 128 + d] += g_ve[(bh << 7) + d];
}

// ---------------- Flash attention fp32, BQ=64, BK=32, 128 threads ----------------
#define FBQ 64
#define FBK 32
#define FQP 132
#define FKP 132
#define FPP 34
#define FLASH_SMEM_BYTES ((64*FQP + FBK*FKP*2 + 64*FPP) * 4)

__global__ void __launch_bounds__(128, 2) flash_kernel()
{
    extern __shared__ float sm[];
    float* Qs = sm;
    float* Ks = Qs + 64 * FQP;
    float* Vs = Ks + FBK * FKP;
    float* Ps = Vs + FBK * FKP;

    const int bh = blockIdx.y;
    const int qb = gridDim.x - 1 - blockIdx.x;
    const int qbase = qb * FBQ;
    const int tid = threadIdx.x;
    const int q = tid >> 1;
    const int half = tid & 1;
    const int tg = qbase + q;

    {
        const float* Qg = g_Q + ((size_t)bh * T_ + tg) * 128 + half * 64;
        float* qd = Qs + q * FQP + half * 64;
#pragma unroll
        for (int u = 0; u < 64; u += 4)
            *(float4*)(qd + u) = *(const float4*)(Qg + u);
    }

    float o[64];
#pragma unroll
    for (int i = 0; i < 64; i++) o[i] = 0.f;
    float rowm = -FLT_MAX, l = 0.f;

    const int nkt = qb * 2 + 2;
    const int lrow = tid >> 2;
    const int lcol = (tid & 3) * 32;
    const int kb = half * 16;

    for (int kt = 0; kt < nkt; ++kt) {
        const int kb0 = kt * FBK;
        {
            const float* Kg = g_K + ((size_t)bh * T_ + kb0 + lrow) * 128 + lcol;
            const float* Vg = g_V + ((size_t)bh * T_ + kb0 + lrow) * 128 + lcol;
            float* kd = Ks + lrow * FKP + lcol;
            float* vd = Vs + lrow * FKP + lcol;
#pragma unroll
            for (int u = 0; u < 32; u += 4) {
                *(float4*)(kd + u) = *(const float4*)(Kg + u);
                *(float4*)(vd + u) = *(const float4*)(Vg + u);
            }
        }
        __syncthreads();

        float s[16];
#pragma unroll
        for (int j = 0; j < 16; j++) s[j] = 0.f;
#pragma unroll 2
        for (int d4 = 0; d4 < 128; d4 += 4) {
            const float4 qv = *(const float4*)(Qs + q * FQP + d4);
#pragma unroll
            for (int j = 0; j < 16; j++) {
                const float4 kv = *(const float4*)(Ks + (kb + j) * FKP + d4);
                s[j] = fmaf(qv.x, kv.x, fmaf(qv.y, kv.y, fmaf(qv.z, kv.z, fmaf(qv.w, kv.w, s[j]))));
            }
        }

        float tmax = -FLT_MAX;
#pragma unroll
        for (int j = 0; j < 16; j++) {
            const int kg = kb0 + kb + j;
            s[j] = (kg <= tg) ? s[j] * 0.08838834764831845f : -FLT_MAX;
            tmax = fmaxf(tmax, s[j]);
        }
        tmax = fmaxf(tmax, __shfl_xor_sync(0xffffffffu, tmax, 1));
        const float newm = fmaxf(rowm, tmax);
        const float corr = expf(rowm - newm);
        float ps = 0.f;
#pragma unroll
        for (int j = 0; j < 16; j++) { const float p = expf(s[j] - newm); s[j] = p; ps += p; }
        ps += __shfl_xor_sync(0xffffffffu, ps, 1);
        l = l * corr + ps;
        rowm = newm;
#pragma unroll
        for (int i = 0; i < 64; i++) o[i] *= corr;

#pragma unroll
        for (int j = 0; j < 16; j++) Ps[q * FPP + kb + j] = s[j];
        __syncwarp();

#pragma unroll 2
        for (int k = 0; k < FBK; k++) {
            const float p = Ps[q * FPP + k];
            const float* vr = Vs + k * FKP + half * 64;
#pragma unroll
            for (int u = 0; u < 64; u += 4) {
                const float4 vv = *(const float4*)(vr + u);
                o[u+0] = fmaf(p, vv.x, o[u+0]);
                o[u+1] = fmaf(p, vv.y, o[u+1]);
                o[u+2] = fmaf(p, vv.z, o[u+2]);
                o[u+3] = fmaf(p, vv.w, o[u+3]);
            }
        }
        __syncthreads();
    }

    const float invl = 1.f / l;
    const int b = bh >> 4, h = bh & 15;
    float* dst = g_AO + ((size_t)(b * T_ + tg)) * HID_ + h * 128 + half * 64;
#pragma unroll
    for (int u = 0; u < 64; u += 4)
        *(float4*)(dst + u) = make_float4(o[u]*invl, o[u+1]*invl, o[u+2]*invl, o[u+3]*invl);
}

// ---------------- launch ----------------
extern "C" void kernel_launch(void* const* d_in, const int* in_sizes, int n_in,
                              void* d_out, int out_size)
{
    (void)in_sizes; (void)n_in; (void)out_size;
    const float* hidden = (const float*)d_in[0];
    const float* q_w = (const float*)d_in[2];
    const float* k_w = (const float*)d_in[3];
    const float* v_w = (const float*)d_in[4];
    const float* o_w = (const float*)d_in[5];
    float* out = (float*)d_out;

    cudaFuncSetAttribute(flash_kernel, cudaFuncAttributeMaxDynamicSharedMemorySize, FLASH_SMEM_BYTES);

    sgemm_nt<1><<<dim3(16, 32, 3), 256>>>(hidden, q_w, k_w, v_w, nullptr);
    rope_kernel<<<32768, 256>>>();
    abar_kernel<<<32, 256>>>();
    cam_prep_kernel<<<1, 128>>>();
    v_update_kernel<<<8192, 256>>>();
    flash_kernel<<<dim3(32, 32), 128, FLASH_SMEM_BYTES>>>();
    sgemm_nt<0><<<dim3(16, 32, 1), 256>>>(nullptr, o_w, nullptr, nullptr, out);
}

// round 6
// speedup vs baseline: 1.2204x; 1.2204x over previous
#include <cuda_runtime.h>
#include <cuda_bf16.h>
#include <math.h>
#include <stdint.h>
#include <float.h>

#define B_  2
#define T_  2048
#define HID_ 2048
#define H_  16
#define D_  128
#define BH_ (B_*H_)
#define BT_ (B_*T_)

// ---------------- device scratch ----------------
__device__ float g_Q[(size_t)BH_ * T_ * D_];
__device__ float g_K[(size_t)BH_ * T_ * D_];
__device__ float g_V[(size_t)BH_ * T_ * D_];
__device__ float g_AO[(size_t)BT_ * HID_];
__device__ float g_Abar[BH_ * T_];
__device__ float g_ve[BH_ * D_];

// split-bf16 operands
__device__ __align__(16) __nv_bfloat16 g_Hh[(size_t)BT_ * HID_];
__device__ __align__(16) __nv_bfloat16 g_Hl[(size_t)BT_ * HID_];
__device__ __align__(16) __nv_bfloat16 g_Wh[3][(size_t)HID_ * HID_];
__device__ __align__(16) __nv_bfloat16 g_Wl[3][(size_t)HID_ * HID_];
__device__ __align__(16) __nv_bfloat16 g_OWh[(size_t)HID_ * HID_];
__device__ __align__(16) __nv_bfloat16 g_OWl[(size_t)HID_ * HID_];
__device__ __align__(16) __nv_bfloat16 g_AOh[(size_t)BT_ * HID_];
__device__ __align__(16) __nv_bfloat16 g_AOl[(size_t)BT_ * HID_];

// ---------------- PTX helpers (compute_103-safe: sm_80-era ISA) ----------------
__device__ __forceinline__ uint32_t smem_u32(const void* p) {
    uint32_t a;
    asm("{ .reg .u64 t; cvta.to.shared.u64 t, %1; cvt.u32.u64 %0, t; }" : "=r"(a) : "l"(p));
    return a;
}
__device__ __forceinline__ void cp_async16(uint32_t dst, const void* src) {
    asm volatile("cp.async.cg.shared.global [%0], [%1], 16;" :: "r"(dst), "l"(src));
}
#define CP_COMMIT() asm volatile("cp.async.commit_group;" ::: "memory")
#define CP_WAIT(N)  asm volatile("cp.async.wait_group %0;" :: "n"(N) : "memory")

#define LDSM_X4(r, addr) \
    asm volatile("ldmatrix.sync.aligned.m8n8.x4.shared.b16 {%0,%1,%2,%3}, [%4];" \
        : "=r"((r)[0]), "=r"((r)[1]), "=r"((r)[2]), "=r"((r)[3]) : "r"(addr))

__device__ __forceinline__ void mma16816(float* c, const uint32_t* a, const uint32_t* b) {
    asm volatile("mma.sync.aligned.m16n8k16.row.col.f32.bf16.bf16.f32 "
        "{%0,%1,%2,%3}, {%4,%5,%6,%7}, {%8,%9}, {%0,%1,%2,%3};"
        : "+f"(c[0]), "+f"(c[1]), "+f"(c[2]), "+f"(c[3])
        : "r"(a[0]), "r"(a[1]), "r"(a[2]), "r"(a[3]), "r"(b[0]), "r"(b[1]));
}

// ---------------- fp32 -> bf16 hi/lo split ----------------
__global__ void convert_split(const float* __restrict__ src, int sel)
{
    const size_t i = ((size_t)blockIdx.x * blockDim.x + threadIdx.x) * 4;
    const float* s = src;
    __nv_bfloat16 *hi, *lo;
    switch (sel) {
        case 0: hi = g_Hh;    lo = g_Hl;    break;
        case 1: hi = g_Wh[0]; lo = g_Wl[0]; break;
        case 2: hi = g_Wh[1]; lo = g_Wl[1]; break;
        case 3: hi = g_Wh[2]; lo = g_Wl[2]; break;
        case 4: hi = g_OWh;   lo = g_OWl;   break;
        default: s = g_AO; hi = g_AOh; lo = g_AOl; break;
    }
    const float4 v = *(const float4*)(s + i);
    const __nv_bfloat16 h0 = __float2bfloat16(v.x), h1 = __float2bfloat16(v.y),
                        h2 = __float2bfloat16(v.z), h3 = __float2bfloat16(v.w);
    const __nv_bfloat16 l0 = __float2bfloat16(v.x - __bfloat162float(h0));
    const __nv_bfloat16 l1 = __float2bfloat16(v.y - __bfloat162float(h1));
    const __nv_bfloat16 l2 = __float2bfloat16(v.z - __bfloat162float(h2));
    const __nv_bfloat16 l3 = __float2bfloat16(v.w - __bfloat162float(h3));
    *(__nv_bfloat162*)(hi + i)     = __nv_bfloat162(h0, h1);
    *(__nv_bfloat162*)(hi + i + 2) = __nv_bfloat162(h2, h3);
    *(__nv_bfloat162*)(lo + i)     = __nv_bfloat162(l0, l1);
    *(__nv_bfloat162*)(lo + i + 2) = __nv_bfloat162(l2, l3);
}

// ---------------- mma.sync split-bf16 GEMM: C[i,j] = sum_k A[i,k]*W[j,k] ----------------
// 128x128 tile, BK=64, 2-stage cp.async pipeline, 8 warps (4m x 2n), warp tile 32x64.
// MODE 1: A = hidden split, W = qkv weight (blockIdx.z), scatter to g_Q/g_K/g_V [b,h,t,d]
// MODE 0: A = AO split, W = o_w, C row-major to d_out
#define GT_TILE  16384            // one operand tile: 128 rows x 64 bf16 x 2B
#define GT_STAGE (4 * GT_TILE)    // Ah, Al, Bh, Bl
#define GT_SMEM  (2 * GT_STAGE)   // 131072 bytes

template<int MODE>
__global__ void __launch_bounds__(256) gemm_mma(float* __restrict__ C)
{
    extern __shared__ char smem[];
    const uint32_t sbase = smem_u32(smem);
    const int tid = threadIdx.x;
    const int wid = tid >> 5;
    const int lane = tid & 31;
    const int m0 = blockIdx.y * 128;
    const int n0 = blockIdx.x * 128;

    const __nv_bfloat16 *Ah, *Al, *Wh, *Wl;
    if (MODE == 1) {
        Ah = g_Hh; Al = g_Hl;
        Wh = g_Wh[blockIdx.z]; Wl = g_Wl[blockIdx.z];
    } else {
        Ah = g_AOh; Al = g_AOl;
        Wh = g_OWh; Wl = g_OWl;
    }

    // loader mapping: part 0=Ah 1=Al 2=Wh 3=Wl; 64 threads/part, 2 rows each, 8x16B per row
    const int part = tid >> 6;
    const int u = tid & 63;
    const __nv_bfloat16* gsrc = (part == 0) ? Ah : (part == 1) ? Al : (part == 2) ? Wh : Wl;
    const int growbase = (part < 2) ? m0 : n0;
    const uint32_t tpart = sbase + part * GT_TILE;

    auto load_stage = [&](int c, int s) {
#pragma unroll
        for (int rr = 0; rr < 2; rr++) {
            const int r = u * 2 + rr;
            const __nv_bfloat16* src = gsrc + (size_t)(growbase + r) * 2048 + c * 64;
            const uint32_t drow = tpart + s * GT_STAGE + r * 128;
#pragma unroll
            for (int g = 0; g < 8; g++)
                cp_async16(drow + (((g ^ (r & 7)) << 4)), src + g * 8);
        }
    };

    const int wm = wid & 3;        // 4 m-warps of 32 rows
    const int wn = wid >> 2;       // 2 n-warps of 64 cols

    float acc[2][8][4];
#pragma unroll
    for (int a = 0; a < 2; a++)
#pragma unroll
        for (int b = 0; b < 8; b++)
#pragma unroll
            for (int cx = 0; cx < 4; cx++) acc[a][b][cx] = 0.f;

    load_stage(0, 0);
    CP_COMMIT();

    for (int c = 0; c < 32; ++c) {
        const int s = c & 1;
        if (c + 1 < 32) {
            load_stage(c + 1, s ^ 1);
            CP_COMMIT();
            CP_WAIT(1);
        } else {
            CP_WAIT(0);
        }
        __syncthreads();

        const uint32_t st = sbase + s * GT_STAGE;
#pragma unroll
        for (int ks = 0; ks < 4; ks++) {
            const int lr = lane & 15;
            const int g = ks * 2 + (lane >> 4);

            uint32_t ah[2][4], al[2][4];
#pragma unroll
            for (int mb = 0; mb < 2; mb++) {
                const int r = wm * 32 + mb * 16 + lr;
                const uint32_t off = r * 128 + (((g ^ (r & 7)) << 4));
                LDSM_X4(ah[mb], st + off);
                LDSM_X4(al[mb], st + GT_TILE + off);
            }
            uint32_t bh[8][2], bl[8][2];
#pragma unroll
            for (int np = 0; np < 4; np++) {
                const int r = wn * 64 + np * 16 + lr;
                const uint32_t off = r * 128 + (((g ^ (r & 7)) << 4));
                uint32_t t4[4];
                LDSM_X4(t4, st + 2 * GT_TILE + off);
                bh[2*np][0] = t4[0]; bh[2*np][1] = t4[2];
                bh[2*np+1][0] = t4[1]; bh[2*np+1][1] = t4[3];
                LDSM_X4(t4, st + 3 * GT_TILE + off);
                bl[2*np][0] = t4[0]; bl[2*np][1] = t4[2];
                bl[2*np+1][0] = t4[1]; bl[2*np+1][1] = t4[3];
            }
#pragma unroll
            for (int mb = 0; mb < 2; mb++)
#pragma unroll
                for (int nb = 0; nb < 8; nb++) {
                    mma16816(acc[mb][nb], ah[mb], bh[nb]);
                    mma16816(acc[mb][nb], ah[mb], bl[nb]);
                    mma16816(acc[mb][nb], al[mb], bh[nb]);
                }
        }
        __syncthreads();
    }

    // epilogue
#pragma unroll
    for (int mb = 0; mb < 2; mb++)
#pragma unroll
        for (int rh = 0; rh < 2; rh++) {
            const int row = wm * 32 + mb * 16 + rh * 8 + (lane >> 2);
            float* dst;
            if (MODE == 1) {
                const int gr = m0 + row;
                const int bb = gr >> 11, t = gr & 2047;
                float* G = (blockIdx.z == 0) ? g_Q : (blockIdx.z == 1) ? g_K : g_V;
                dst = G + (((size_t)(bb * H_ + blockIdx.x) * T_ + t) << 7);
            } else {
                dst = C + (size_t)(m0 + row) * 2048 + n0;
            }
            const int cbase = wn * 64 + (lane & 3) * 2;
#pragma unroll
            for (int nb = 0; nb < 8; nb++)
                *(float2*)(dst + cbase + nb * 8) =
                    make_float2(acc[mb][nb][rh * 2], acc[mb][nb][rh * 2 + 1]);
        }
}

// ---------------- RoPE in place on Q and K ----------------
__global__ void rope_kernel()
{
    const int idx = blockIdx.x * blockDim.x + threadIdx.x;
    const int per = BH_ * T_ * 64;
    float* P = (idx < per) ? g_Q : g_K;
    const int i = (idx < per) ? idx : idx - per;
    const int j = i & 63;
    const int bht = i >> 6;
    const int t = bht & (T_ - 1);
    const float inv = powf(10000.f, -(float)j * (1.f / 64.f));
    float s, c;
    sincosf((float)t * inv, &s, &c);
    float* row = P + (size_t)bht * 128;
    const float x1 = row[j];
    const float x2 = row[j + 64];
    row[j]      = x1 * c - x2 * s;
    row[j + 64] = x2 * c + x1 * s;
}

// ---------------- A_bar: softmax of last query row per (b,h) ----------------
__global__ void __launch_bounds__(256) abar_kernel()
{
    const int bh = blockIdx.x;
    __shared__ float qrow[128];
    __shared__ float sc[2048];
    __shared__ float red[256];
    const int tid = threadIdx.x;

    const float* Qr = g_Q + ((size_t)bh * T_ + (T_ - 1)) * 128;
    if (tid < 128) qrow[tid] = Qr[tid];
    __syncthreads();

    for (int k = tid; k < 2048; k += 256) {
        const float4* kr = (const float4*)(g_K + ((size_t)bh * T_ + k) * 128);
        const float4* qr = (const float4*)qrow;
        float s = 0.f;
#pragma unroll
        for (int i = 0; i < 32; i++) {
            const float4 kv = kr[i], qv = qr[i];
            s = fmaf(kv.x, qv.x, s); s = fmaf(kv.y, qv.y, s);
            s = fmaf(kv.z, qv.z, s); s = fmaf(kv.w, qv.w, s);
        }
        sc[k] = s * 0.08838834764831845f;
    }
    __syncthreads();

    float m = -FLT_MAX;
    for (int k = tid; k < 2048; k += 256) m = fmaxf(m, sc[k]);
    red[tid] = m; __syncthreads();
    for (int o = 128; o > 0; o >>= 1) { if (tid < o) red[tid] = fmaxf(red[tid], red[tid + o]); __syncthreads(); }
    const float gm = red[0];
    __syncthreads();

    float sum = 0.f;
    for (int k = tid; k < 2048; k += 256) { const float p = expf(sc[k] - gm); sc[k] = p; sum += p; }
    red[tid] = sum; __syncthreads();
    for (int o = 128; o > 0; o >>= 1) { if (tid < o) red[tid] += red[tid + o]; __syncthreads(); }
    const float invs = 1.f / red[0];

    for (int k = tid; k < 2048; k += 256) g_Abar[bh * 2048 + k] = sc[k] * invs;
}

// ---------------- CAM prep: partitionable threefry2x32 bernoulli ----------------
__device__ __forceinline__ uint32_t rotl32(uint32_t x, int r) { return (x << r) | (x >> (32 - r)); }

__global__ void cam_prep_kernel()
{
    __shared__ float maskv[32];
    const int tid = threadIdx.x;

    if (tid < 32) {
        const float* ab = g_Abar + tid * 2048;
        float sum = 0.f;
        for (int i = 1536; i < 2048; i++) sum += ab[i];
        const float avg = fmaxf(sum * (1.f / 512.f), 1e-6f);
        float p = ab[1535] / avg;
        p = fminf(fmaxf(p, 0.f), 1.f);

        uint32_t x0 = 0u, x1 = (uint32_t)tid;
        const uint32_t k0 = 0u, k1 = 42u, k2 = 0x1BD11BDAu ^ k0 ^ k1;
        x0 += k0; x1 += k1;
#define TF4(a,b,c,d)  x0+=x1; x1=rotl32(x1,a); x1^=x0; \
                      x0+=x1; x1=rotl32(x1,b); x1^=x0; \
                      x0+=x1; x1=rotl32(x1,c); x1^=x0; \
                      x0+=x1; x1=rotl32(x1,d); x1^=x0;
        TF4(13,15,26,6)   x0 += k1; x1 += k2 + 1u;
        TF4(17,29,16,24)  x0 += k2; x1 += k0 + 2u;
        TF4(13,15,26,6)   x0 += k0; x1 += k1 + 3u;
        TF4(17,29,16,24)  x0 += k1; x1 += k2 + 4u;
        TF4(13,15,26,6)   x0 += k2; x1 += k0 + 5u;
#undef TF4
        const uint32_t bits = x0 ^ x1;
        float uu = __uint_as_float((bits >> 9) | 0x3f800000u) - 1.0f;
        uu = fmaxf(uu, 0.f);
        maskv[tid] = (uu < p) ? 1.f : 0.f;
    }
    __syncthreads();

    for (int i = tid; i < 32 * 128; i += blockDim.x) {
        const int bh = i >> 7, d = i & 127;
        g_ve[i] = g_V[((size_t)bh * T_ + 1535) * 128 + d] * maskv[bh] * (1.f / 512.f);
    }
}

__global__ void v_update_kernel()
{
    const int idx = blockIdx.x * blockDim.x + threadIdx.x;
    const int bh = idx >> 16;
    const int rest = idx & 65535;
    const int r = rest >> 7;
    const int d = rest & 127;
    g_V[((size_t)bh * T_ + 1536 + r) * 128 + d] += g_ve[(bh << 7) + d];
}

// ---------------- Flash attention fp32, BQ=64, BK=32, 128 threads ----------------
#define FBQ 64
#define FBK 32
#define FQP 132
#define FKP 132
#define FPP 34
#define FLASH_SMEM_BYTES ((64*FQP + FBK*FKP*2 + 64*FPP) * 4)

__global__ void __launch_bounds__(128, 2) flash_kernel()
{
    extern __shared__ float sm[];
    float* Qs = sm;
    float* Ks = Qs + 64 * FQP;
    float* Vs = Ks + FBK * FKP;
    float* Ps = Vs + FBK * FKP;

    const int bh = blockIdx.y;
    const int qb = gridDim.x - 1 - blockIdx.x;
    const int qbase = qb * FBQ;
    const int tid = threadIdx.x;
    const int q = tid >> 1;
    const int half = tid & 1;
    const int tg = qbase + q;

    {
        const float* Qg = g_Q + ((size_t)bh * T_ + tg) * 128 + half * 64;
        float* qd = Qs + q * FQP + half * 64;
#pragma unroll
        for (int u = 0; u < 64; u += 4)
            *(float4*)(qd + u) = *(const float4*)(Qg + u);
    }

    float o[64];
#pragma unroll
    for (int i = 0; i < 64; i++) o[i] = 0.f;
    float rowm = -FLT_MAX, l = 0.f;

    const int nkt = qb * 2 + 2;
    const int lrow = tid >> 2;
    const int lcol = (tid & 3) * 32;
    const int kb = half * 16;

    for (int kt = 0; kt < nkt; ++kt) {
        const int kb0 = kt * FBK;
        {
            const float* Kg = g_K + ((size_t)bh * T_ + kb0 + lrow) * 128 + lcol;
            const float* Vg = g_V + ((size_t)bh * T_ + kb0 + lrow) * 128 + lcol;
            float* kd = Ks + lrow * FKP + lcol;
            float* vd = Vs + lrow * FKP + lcol;
#pragma unroll
            for (int u = 0; u < 32; u += 4) {
                *(float4*)(kd + u) = *(const float4*)(Kg + u);
                *(float4*)(vd + u) = *(const float4*)(Vg + u);
            }
        }
        __syncthreads();

        float s[16];
#pragma unroll
        for (int j = 0; j < 16; j++) s[j] = 0.f;
#pragma unroll 2
        for (int d4 = 0; d4 < 128; d4 += 4) {
            const float4 qv = *(const float4*)(Qs + q * FQP + d4);
#pragma unroll
            for (int j = 0; j < 16; j++) {
                const float4 kv = *(const float4*)(Ks + (kb + j) * FKP + d4);
                s[j] = fmaf(qv.x, kv.x, fmaf(qv.y, kv.y, fmaf(qv.z, kv.z, fmaf(qv.w, kv.w, s[j]))));
            }
        }

        float tmax = -FLT_MAX;
#pragma unroll
        for (int j = 0; j < 16; j++) {
            const int kg = kb0 + kb + j;
            s[j] = (kg <= tg) ? s[j] * 0.08838834764831845f : -FLT_MAX;
            tmax = fmaxf(tmax, s[j]);
        }
        tmax = fmaxf(tmax, __shfl_xor_sync(0xffffffffu, tmax, 1));
        const float newm = fmaxf(rowm, tmax);
        const float corr = expf(rowm - newm);
        float ps = 0.f;
#pragma unroll
        for (int j = 0; j < 16; j++) { const float p = expf(s[j] - newm); s[j] = p; ps += p; }
        ps += __shfl_xor_sync(0xffffffffu, ps, 1);
        l = l * corr + ps;
        rowm = newm;
#pragma unroll
        for (int i = 0; i < 64; i++) o[i] *= corr;

#pragma unroll
        for (int j = 0; j < 16; j++) Ps[q * FPP + kb + j] = s[j];
        __syncwarp();

#pragma unroll 2
        for (int k = 0; k < FBK; k++) {
            const float p = Ps[q * FPP + k];
            const float* vr = Vs + k * FKP + half * 64;
#pragma unroll
            for (int u = 0; u < 64; u += 4) {
                const float4 vv = *(const float4*)(vr + u);
                o[u+0] = fmaf(p, vv.x, o[u+0]);
                o[u+1] = fmaf(p, vv.y, o[u+1]);
                o[u+2] = fmaf(p, vv.z, o[u+2]);
                o[u+3] = fmaf(p, vv.w, o[u+3]);
            }
        }
        __syncthreads();
    }

    const float invl = 1.f / l;
    const int b = bh >> 4, h = bh & 15;
    float* dst = g_AO + ((size_t)(b * T_ + tg)) * HID_ + h * 128 + half * 64;
#pragma unroll
    for (int u = 0; u < 64; u += 4)
        *(float4*)(dst + u) = make_float4(o[u]*invl, o[u+1]*invl, o[u+2]*invl, o[u+3]*invl);
}

// ---------------- launch ----------------
extern "C" void kernel_launch(void* const* d_in, const int* in_sizes, int n_in,
                              void* d_out, int out_size)
{
    (void)in_sizes; (void)n_in; (void)out_size;
    const float* hidden = (const float*)d_in[0];
    const float* q_w = (const float*)d_in[2];
    const float* k_w = (const float*)d_in[3];
    const float* v_w = (const float*)d_in[4];
    const float* o_w = (const float*)d_in[5];
    float* out = (float*)d_out;

    cudaFuncSetAttribute(flash_kernel, cudaFuncAttributeMaxDynamicSharedMemorySize, FLASH_SMEM_BYTES);
    cudaFuncSetAttribute(gemm_mma<1>, cudaFuncAttributeMaxDynamicSharedMemorySize, GT_SMEM);
    cudaFuncSetAttribute(gemm_mma<0>, cudaFuncAttributeMaxDynamicSharedMemorySize, GT_SMEM);

    convert_split<<<8192, 256>>>(hidden, 0);
    convert_split<<<4096, 256>>>(q_w, 1);
    convert_split<<<4096, 256>>>(k_w, 2);
    convert_split<<<4096, 256>>>(v_w, 3);
    convert_split<<<4096, 256>>>(o_w, 4);

    gemm_mma<1><<<dim3(16, 32, 3), 256, GT_SMEM>>>(nullptr);
    rope_kernel<<<32768, 256>>>();
    abar_kernel<<<32, 256>>>();
    cam_prep_kernel<<<1, 128>>>();
    v_update_kernel<<<8192, 256>>>();
    flash_kernel<<<dim3(32, 32), 128, FLASH_SMEM_BYTES>>>();
    convert_split<<<8192, 256>>>(nullptr, 5);
    gemm_mma<0><<<dim3(16, 32, 1), 256, GT_SMEM>>>(out);
}

// round 7
// speedup vs baseline: 2.0417x; 1.6730x over previous
#include <cuda_runtime.h>
#include <cuda_bf16.h>
#include <math.h>
#include <stdint.h>
#include <float.h>

#define B_  2
#define T_  2048
#define HID_ 2048
#define H_  16
#define D_  128
#define BH_ (B_*H_)
#define BT_ (B_*T_)
#define TT_ 4194304   // T*T

// ---------------- device scratch ----------------
__device__ float g_Q[(size_t)BH_ * T_ * D_];
__device__ float g_K[(size_t)BH_ * T_ * D_];
__device__ float g_V[(size_t)BH_ * T_ * D_];
__device__ float g_AO[(size_t)BT_ * HID_];
__device__ float g_S[(size_t)BH_ * TT_];          // scores scratch (lower tiles valid)

// split-bf16 operands
__device__ __align__(16) __nv_bfloat16 g_Hh[(size_t)BT_ * HID_];
__device__ __align__(16) __nv_bfloat16 g_Hl[(size_t)BT_ * HID_];
__device__ __align__(16) __nv_bfloat16 g_Wh[3][(size_t)HID_ * HID_];
__device__ __align__(16) __nv_bfloat16 g_Wl[3][(size_t)HID_ * HID_];
__device__ __align__(16) __nv_bfloat16 g_OWh[(size_t)HID_ * HID_];
__device__ __align__(16) __nv_bfloat16 g_OWl[(size_t)HID_ * HID_];
__device__ __align__(16) __nv_bfloat16 g_AOh[(size_t)BT_ * HID_];
__device__ __align__(16) __nv_bfloat16 g_AOl[(size_t)BT_ * HID_];
__device__ __align__(16) __nv_bfloat16 g_Qh[(size_t)BH_ * T_ * D_];
__device__ __align__(16) __nv_bfloat16 g_Ql[(size_t)BH_ * T_ * D_];
__device__ __align__(16) __nv_bfloat16 g_Kh[(size_t)BH_ * T_ * D_];
__device__ __align__(16) __nv_bfloat16 g_Kl[(size_t)BH_ * T_ * D_];
__device__ __align__(16) __nv_bfloat16 g_Vth[(size_t)BH_ * D_ * T_]; // [bh][d][k]
__device__ __align__(16) __nv_bfloat16 g_Vtl[(size_t)BH_ * D_ * T_];
__device__ __align__(16) __nv_bfloat16 g_Ph[(size_t)BH_ * TT_];      // probs split
__device__ __align__(16) __nv_bfloat16 g_Pl[(size_t)BH_ * TT_];

// ---------------- PTX helpers (compute_103-safe) ----------------
__device__ __forceinline__ uint32_t smem_u32(const void* p) {
    uint32_t a;
    asm("{ .reg .u64 t; cvta.to.shared.u64 t, %1; cvt.u32.u64 %0, t; }" : "=r"(a) : "l"(p));
    return a;
}
__device__ __forceinline__ void cp_async16(uint32_t dst, const void* src) {
    asm volatile("cp.async.cg.shared.global [%0], [%1], 16;" :: "r"(dst), "l"(src));
}
#define CP_COMMIT() asm volatile("cp.async.commit_group;" ::: "memory")
#define CP_WAIT(N)  asm volatile("cp.async.wait_group %0;" :: "n"(N) : "memory")

#define LDSM_X4(r, addr) \
    asm volatile("ldmatrix.sync.aligned.m8n8.x4.shared.b16 {%0,%1,%2,%3}, [%4];" \
        : "=r"((r)[0]), "=r"((r)[1]), "=r"((r)[2]), "=r"((r)[3]) : "r"(addr))

__device__ __forceinline__ void mma16816(float* c, const uint32_t* a, const uint32_t* b) {
    asm volatile("mma.sync.aligned.m16n8k16.row.col.f32.bf16.bf16.f32 "
        "{%0,%1,%2,%3}, {%4,%5,%6,%7}, {%8,%9}, {%0,%1,%2,%3};"
        : "+f"(c[0]), "+f"(c[1]), "+f"(c[2]), "+f"(c[3])
        : "r"(a[0]), "r"(a[1]), "r"(a[2]), "r"(a[3]), "r"(b[0]), "r"(b[1]));
}

__device__ __forceinline__ void split2(float x, __nv_bfloat16& h, __nv_bfloat16& l) {
    h = __float2bfloat16(x);
    l = __float2bfloat16(x - __bfloat162float(h));
}

// ---------------- merged fp32 -> bf16 hi/lo split for inputs ----------------
__global__ void convert_all(const float* __restrict__ hs,
                            const float* __restrict__ qw, const float* __restrict__ kw,
                            const float* __restrict__ vw, const float* __restrict__ ow)
{
    const int sel = blockIdx.y;
    if (sel > 0 && blockIdx.x >= 4096) return;
    const size_t i = ((size_t)blockIdx.x * blockDim.x + threadIdx.x) * 4;
    const float* s;
    __nv_bfloat16 *hi, *lo;
    switch (sel) {
        case 0: s = hs; hi = g_Hh;    lo = g_Hl;    break;
        case 1: s = qw; hi = g_Wh[0]; lo = g_Wl[0]; break;
        case 2: s = kw; hi = g_Wh[1]; lo = g_Wl[1]; break;
        case 3: s = vw; hi = g_Wh[2]; lo = g_Wl[2]; break;
        default: s = ow; hi = g_OWh;  lo = g_OWl;   break;
    }
    const float4 v = *(const float4*)(s + i);
    __nv_bfloat16 h0,h1,h2,h3,l0,l1,l2,l3;
    split2(v.x,h0,l0); split2(v.y,h1,l1); split2(v.z,h2,l2); split2(v.w,h3,l3);
    *(__nv_bfloat162*)(hi + i)     = __nv_bfloat162(h0, h1);
    *(__nv_bfloat162*)(hi + i + 2) = __nv_bfloat162(h2, h3);
    *(__nv_bfloat162*)(lo + i)     = __nv_bfloat162(l0, l1);
    *(__nv_bfloat162*)(lo + i + 2) = __nv_bfloat162(l2, l3);
}

__global__ void convert_ao()
{
    const size_t i = ((size_t)blockIdx.x * blockDim.x + threadIdx.x) * 4;
    const float4 v = *(const float4*)(g_AO + i);
    __nv_bfloat16 h0,h1,h2,h3,l0,l1,l2,l3;
    split2(v.x,h0,l0); split2(v.y,h1,l1); split2(v.z,h2,l2); split2(v.w,h3,l3);
    *(__nv_bfloat162*)(g_AOh + i)     = __nv_bfloat162(h0, h1);
    *(__nv_bfloat162*)(g_AOh + i + 2) = __nv_bfloat162(h2, h3);
    *(__nv_bfloat162*)(g_AOl + i)     = __nv_bfloat162(l0, l1);
    *(__nv_bfloat162*)(g_AOl + i + 2) = __nv_bfloat162(l2, l3);
}

// split Q,K (post-rope) into bf16 hi/lo
__global__ void convert_qk()
{
    const size_t i = ((size_t)blockIdx.x * blockDim.x + threadIdx.x) * 4;
    const float* s = blockIdx.y ? g_K : g_Q;
    __nv_bfloat16* hi = blockIdx.y ? g_Kh : g_Qh;
    __nv_bfloat16* lo = blockIdx.y ? g_Kl : g_Ql;
    const float4 v = *(const float4*)(s + i);
    __nv_bfloat16 h0,h1,h2,h3,l0,l1,l2,l3;
    split2(v.x,h0,l0); split2(v.y,h1,l1); split2(v.z,h2,l2); split2(v.w,h3,l3);
    *(__nv_bfloat162*)(hi + i)     = __nv_bfloat162(h0, h1);
    *(__nv_bfloat162*)(hi + i + 2) = __nv_bfloat162(h2, h3);
    *(__nv_bfloat162*)(lo + i)     = __nv_bfloat162(l0, l1);
    *(__nv_bfloat162*)(lo + i + 2) = __nv_bfloat162(l2, l3);
}

// V (post-update) -> transposed split: Vt[bh][d][k]
__global__ void __launch_bounds__(256) convert_vt()
{
    __shared__ float tile[64][65];
    const int bh = blockIdx.y;
    const int kt = blockIdx.x >> 1;          // 32 k-tiles of 64
    const int dt = blockIdx.x & 1;           // 2 d-tiles of 64
    const int k0 = kt * 64, d0 = dt * 64;
    const int tid = threadIdx.x;

    for (int idx = tid; idx < 64 * 64; idx += 256) {
        const int i = idx >> 6, j = idx & 63;
        tile[i][j] = g_V[((size_t)bh * T_ + k0 + i) * 128 + d0 + j];
    }
    __syncthreads();
    for (int idx = tid; idx < 64 * 64; idx += 256) {
        const int j = idx >> 6, i = idx & 63;     // write coalesced over i (k)
        const float x = tile[i][j];
        __nv_bfloat16 h, l; split2(x, h, l);
        const size_t o = ((size_t)bh * D_ + d0 + j) * T_ + k0 + i;
        g_Vth[o] = h; g_Vtl[o] = l;
    }
}

// ---------------- unified mma.sync split-bf16 GEMM ----------------
// MODE 1: QKV proj   (grid 16,32,3)  -> scatter to g_Q/g_K/g_V [b,h,t,d]
// MODE 0: O proj     (grid 16,32)    -> C row-major (d_out)
// MODE 2: S = Q K^T  (grid 136,32)   -> g_S lower tiles, per bh
// MODE 3: AO = P V   (grid 16,32)    -> g_AO [b,t,h*d], per bh, causal k-range
#define GT_TILE  16384
#define GT_STAGE (4 * GT_TILE)
#define GT_SMEM  (2 * GT_STAGE)

template<int MODE>
__global__ void __launch_bounds__(256) gemm_mma(float* __restrict__ C)
{
    extern __shared__ char smem[];
    const uint32_t sbase = smem_u32(smem);
    const int tid = threadIdx.x;
    const int wid = tid >> 5;
    const int lane = tid & 31;

    int mloc, nloc, bh = 0, kchunks, arowbase, browbase, astr, bstr;
    const __nv_bfloat16 *Ahp, *Alp, *Bhp, *Blp;

    if (MODE == 1) {
        mloc = blockIdx.y * 128; nloc = blockIdx.x * 128;
        arowbase = mloc; browbase = nloc; astr = 2048; bstr = 2048; kchunks = 32;
        Ahp = g_Hh; Alp = g_Hl; Bhp = g_Wh[blockIdx.z]; Blp = g_Wl[blockIdx.z];
    } else if (MODE == 0) {
        mloc = blockIdx.y * 128; nloc = blockIdx.x * 128;
        arowbase = mloc; browbase = nloc; astr = 2048; bstr = 2048; kchunks = 32;
        Ahp = g_AOh; Alp = g_AOl; Bhp = g_OWh; Blp = g_OWl;
    } else if (MODE == 2) {
        bh = blockIdx.y;
        const int x = blockIdx.x;
        int i = (int)((sqrtf(8.f * x + 1.f) - 1.f) * 0.5f);
        while ((i + 1) * (i + 2) / 2 <= x) ++i;
        while (i * (i + 1) / 2 > x) --i;
        const int j = x - i * (i + 1) / 2;
        mloc = i * 128; nloc = j * 128;
        arowbase = bh * 2048 + mloc; browbase = bh * 2048 + nloc;
        astr = 128; bstr = 128; kchunks = 2;
        Ahp = g_Qh; Alp = g_Ql; Bhp = g_Kh; Blp = g_Kl;
    } else {
        bh = blockIdx.y;
        mloc = blockIdx.x * 128; nloc = 0;
        arowbase = bh * 2048 + mloc; browbase = bh * 128;
        astr = 2048; bstr = 2048; kchunks = 2 * (blockIdx.x + 1);
        Ahp = g_Ph; Alp = g_Pl; Bhp = g_Vth; Blp = g_Vtl;
    }

    const int part = tid >> 6;
    const int u = tid & 63;
    const __nv_bfloat16* gsrc = (part == 0) ? Ahp : (part == 1) ? Alp : (part == 2) ? Bhp : Blp;
    const int growbase = (part < 2) ? arowbase : browbase;
    const int gstride  = (part < 2) ? astr : bstr;
    const uint32_t tpart = sbase + part * GT_TILE;

    auto load_stage = [&](int c, int s) {
#pragma unroll
        for (int rr = 0; rr < 2; rr++) {
            const int r = u * 2 + rr;
            const __nv_bfloat16* src = gsrc + (size_t)(growbase + r) * gstride + c * 64;
            const uint32_t drow = tpart + s * GT_STAGE + r * 128;
#pragma unroll
            for (int g = 0; g < 8; g++)
                cp_async16(drow + (((g ^ (r & 7)) << 4)), src + g * 8);
        }
    };

    const int wm = wid & 3;
    const int wn = wid >> 2;

    float acc[2][8][4];
#pragma unroll
    for (int a = 0; a < 2; a++)
#pragma unroll
        for (int b = 0; b < 8; b++)
#pragma unroll
            for (int cx = 0; cx < 4; cx++) acc[a][b][cx] = 0.f;

    load_stage(0, 0);
    CP_COMMIT();

    for (int c = 0; c < kchunks; ++c) {
        const int s = c & 1;
        if (c + 1 < kchunks) {
            load_stage(c + 1, s ^ 1);
            CP_COMMIT();
            CP_WAIT(1);
        } else {
            CP_WAIT(0);
        }
        __syncthreads();

        const uint32_t st = sbase + s * GT_STAGE;
#pragma unroll
        for (int ks = 0; ks < 4; ks++) {
            const int lr = lane & 15;
            const int g = ks * 2 + (lane >> 4);

            uint32_t ah[2][4], al[2][4];
#pragma unroll
            for (int mb = 0; mb < 2; mb++) {
                const int r = wm * 32 + mb * 16 + lr;
                const uint32_t off = r * 128 + (((g ^ (r & 7)) << 4));
                LDSM_X4(ah[mb], st + off);
                LDSM_X4(al[mb], st + GT_TILE + off);
            }
            uint32_t bhf[8][2], blf[8][2];
#pragma unroll
            for (int np = 0; np < 4; np++) {
                const int r = wn * 64 + np * 16 + lr;
                const uint32_t off = r * 128 + (((g ^ (r & 7)) << 4));
                uint32_t t4[4];
                LDSM_X4(t4, st + 2 * GT_TILE + off);
                bhf[2*np][0] = t4[0]; bhf[2*np][1] = t4[2];
                bhf[2*np+1][0] = t4[1]; bhf[2*np+1][1] = t4[3];
                LDSM_X4(t4, st + 3 * GT_TILE + off);
                blf[2*np][0] = t4[0]; blf[2*np][1] = t4[2];
                blf[2*np+1][0] = t4[1]; blf[2*np+1][1] = t4[3];
            }
#pragma unroll
            for (int mb = 0; mb < 2; mb++)
#pragma unroll
                for (int nb = 0; nb < 8; nb++) {
                    mma16816(acc[mb][nb], ah[mb], bhf[nb]);
                    mma16816(acc[mb][nb], ah[mb], blf[nb]);
                    mma16816(acc[mb][nb], al[mb], bhf[nb]);
                }
        }
        __syncthreads();
    }

    // epilogue
#pragma unroll
    for (int mb = 0; mb < 2; mb++)
#pragma unroll
        for (int rh = 0; rh < 2; rh++) {
            const int row = wm * 32 + mb * 16 + rh * 8 + (lane >> 2);
            float* dst;
            if (MODE == 1) {
                const int gr = mloc + row;
                const int bb = gr >> 11, t = gr & 2047;
                float* G = (blockIdx.z == 0) ? g_Q : (blockIdx.z == 1) ? g_K : g_V;
                dst = G + (((size_t)(bb * H_ + blockIdx.x) * T_ + t) << 7);
            } else if (MODE == 0) {
                dst = C + (size_t)(mloc + row) * 2048 + nloc;
            } else if (MODE == 2) {
                dst = g_S + (size_t)bh * TT_ + (size_t)(mloc + row) * 2048 + nloc;
            } else {
                const int t = mloc + row;
                const int bb = bh >> 4, h = bh & 15;
                dst = g_AO + ((size_t)(bb * T_ + t)) * 2048 + h * 128;
            }
            const int cbase = wn * 64 + (lane & 3) * 2;
#pragma unroll
            for (int nb = 0; nb < 8; nb++)
                *(float2*)(dst + cbase + nb * 8) =
                    make_float2(acc[mb][nb][rh * 2], acc[mb][nb][rh * 2 + 1]);
        }
}

// ---------------- RoPE in place on Q and K ----------------
__global__ void rope_kernel()
{
    const int idx = blockIdx.x * blockDim.x + threadIdx.x;
    const int per = BH_ * T_ * 64;
    float* P = (idx < per) ? g_Q : g_K;
    const int i = (idx < per) ? idx : idx - per;
    const int j = i & 63;
    const int bht = i >> 6;
    const int t = bht & (T_ - 1);
    const float inv = powf(10000.f, -(float)j * (1.f / 64.f));
    float s, c;
    sincosf((float)t * inv, &s, &c);
    float* row = P + (size_t)bht * 128;
    const float x1 = row[j];
    const float x2 = row[j + 64];
    row[j]      = x1 * c - x2 * s;
    row[j + 64] = x2 * c + x1 * s;
}

// ---------------- fused A_bar softmax + CAM bernoulli + V update ----------------
__device__ __forceinline__ uint32_t rotl32(uint32_t x, int r) { return (x << r) | (x >> (32 - r)); }

__global__ void __launch_bounds__(256) abar_cam_v()
{
    const int bh = blockIdx.x;
    __shared__ float qrow[128];
    __shared__ float sc[2048];
    __shared__ float red[256];
    __shared__ float maskf;
    __shared__ float vev[128];
    const int tid = threadIdx.x;

    const float* Qr = g_Q + ((size_t)bh * T_ + (T_ - 1)) * 128;
    if (tid < 128) qrow[tid] = Qr[tid];
    __syncthreads();

    for (int k = tid; k < 2048; k += 256) {
        const float4* kr = (const float4*)(g_K + ((size_t)bh * T_ + k) * 128);
        const float4* qr = (const float4*)qrow;
        float s = 0.f;
#pragma unroll
        for (int i = 0; i < 32; i++) {
            const float4 kv = kr[i], qv = qr[i];
            s = fmaf(kv.x, qv.x, s); s = fmaf(kv.y, qv.y, s);
            s = fmaf(kv.z, qv.z, s); s = fmaf(kv.w, qv.w, s);
        }
        sc[k] = s * 0.08838834764831845f;
    }
    __syncthreads();

    float m = -FLT_MAX;
    for (int k = tid; k < 2048; k += 256) m = fmaxf(m, sc[k]);
    red[tid] = m; __syncthreads();
    for (int o = 128; o > 0; o >>= 1) { if (tid < o) red[tid] = fmaxf(red[tid], red[tid + o]); __syncthreads(); }
    const float gm = red[0];
    __syncthreads();

    float sum = 0.f;
    for (int k = tid; k < 2048; k += 256) { const float p = expf(sc[k] - gm); sc[k] = p; sum += p; }
    red[tid] = sum; __syncthreads();
    for (int o = 128; o > 0; o >>= 1) { if (tid < o) red[tid] += red[tid + o]; __syncthreads(); }
    const float invs = 1.f / red[0];
    __syncthreads();

    for (int k = tid; k < 2048; k += 256) sc[k] *= invs;
    __syncthreads();

    // window sum over [1536,2048)
    float ws = 0.f;
    for (int k = 1536 + tid; k < 2048; k += 256) ws += sc[k];
    red[tid] = ws; __syncthreads();
    for (int o = 128; o > 0; o >>= 1) { if (tid < o) red[tid] += red[tid + o]; __syncthreads(); }

    if (tid == 0) {
        const float avg = fmaxf(red[0] * (1.f / 512.f), 1e-6f);
        float p = fminf(fmaxf(sc[1535] / avg, 0.f), 1.f);
        // partitionable threefry2x32: (x0,x1)=threefry((0,42),(0,bh)); bits=x0^x1
        uint32_t x0 = 0u, x1 = (uint32_t)bh;
        const uint32_t k0 = 0u, k1 = 42u, k2 = 0x1BD11BDAu ^ k0 ^ k1;
        x0 += k0; x1 += k1;
#define TF4(a,b,c,d)  x0+=x1; x1=rotl32(x1,a); x1^=x0; \
                      x0+=x1; x1=rotl32(x1,b); x1^=x0; \
                      x0+=x1; x1=rotl32(x1,c); x1^=x0; \
                      x0+=x1; x1=rotl32(x1,d); x1^=x0;
        TF4(13,15,26,6)   x0 += k1; x1 += k2 + 1u;
        TF4(17,29,16,24)  x0 += k2; x1 += k0 + 2u;
        TF4(13,15,26,6)   x0 += k0; x1 += k1 + 3u;
        TF4(17,29,16,24)  x0 += k1; x1 += k2 + 4u;
        TF4(13,15,26,6)   x0 += k2; x1 += k0 + 5u;
#undef TF4
        const uint32_t bits = x0 ^ x1;
        float uu = __uint_as_float((bits >> 9) | 0x3f800000u) - 1.0f;
        uu = fmaxf(uu, 0.f);
        maskf = (uu < p) ? 1.f : 0.f;
    }
    __syncthreads();

    if (tid < 128) vev[tid] = g_V[((size_t)bh * T_ + 1535) * 128 + tid] * maskf * (1.f / 512.f);
    __syncthreads();

    for (int idx = tid; idx < 512 * 128; idx += 256) {
        const int r = idx >> 7, d = idx & 127;
        g_V[((size_t)bh * T_ + 1536 + r) * 128 + d] += vev[d];
    }
}

// ---------------- row softmax: S -> split-bf16 P (zero-padded to tile) ----------------
__global__ void __launch_bounds__(128) softmax_rows()
{
    const int gid = blockIdx.x;
    const int bh = gid >> 11;
    const int t = gid & 2047;
    const int n = t + 1;
    const int padend = ((t >> 7) + 1) << 7;
    const float* srow = g_S + (size_t)bh * TT_ + (size_t)t * 2048;
    __nv_bfloat16* ph = g_Ph + (size_t)bh * TT_ + (size_t)t * 2048;
    __nv_bfloat16* pl = g_Pl + (size_t)bh * TT_ + (size_t)t * 2048;

    __shared__ float e[2048];
    __shared__ float red[4];
    const int tid = threadIdx.x;
    const int wid = tid >> 5, lane = tid & 31;
    const float scale = 0.08838834764831845f;

    float m = -FLT_MAX;
    for (int k = tid; k < n; k += 128) {
        const float v = srow[k] * scale;
        e[k] = v;
        m = fmaxf(m, v);
    }
#pragma unroll
    for (int o = 16; o > 0; o >>= 1) m = fmaxf(m, __shfl_xor_sync(0xffffffffu, m, o));
    if (lane == 0) red[wid] = m;
    __syncthreads();
    m = fmaxf(fmaxf(red[0], red[1]), fmaxf(red[2], red[3]));
    __syncthreads();

    float sum = 0.f;
    for (int k = tid; k < n; k += 128) {
        const float p = expf(e[k] - m);
        e[k] = p;
        sum += p;
    }
#pragma unroll
    for (int o = 16; o > 0; o >>= 1) sum += __shfl_xor_sync(0xffffffffu, sum, o);
    if (lane == 0) red[wid] = sum;
    __syncthreads();
    const float inv = 1.f / (red[0] + red[1] + red[2] + red[3]);

    for (int k = tid; k < padend; k += 128) {
        if (k < n) {
            const float p = e[k] * inv;
            __nv_bfloat16 h, l; split2(p, h, l);
            ph[k] = h; pl[k] = l;
        } else {
            ph[k] = __float2bfloat16(0.f);
            pl[k] = __float2bfloat16(0.f);
        }
    }
}

// ---------------- launch ----------------
extern "C" void kernel_launch(void* const* d_in, const int* in_sizes, int n_in,
                              void* d_out, int out_size)
{
    (void)in_sizes; (void)n_in; (void)out_size;
    const float* hidden = (const float*)d_in[0];
    const float* q_w = (const float*)d_in[2];
    const float* k_w = (const float*)d_in[3];
    const float* v_w = (const float*)d_in[4];
    const float* o_w = (const float*)d_in[5];
    float* out = (float*)d_out;

    cudaFuncSetAttribute(gemm_mma<0>, cudaFuncAttributeMaxDynamicSharedMemorySize, GT_SMEM);
    cudaFuncSetAttribute(gemm_mma<1>, cudaFuncAttributeMaxDynamicSharedMemorySize, GT_SMEM);
    cudaFuncSetAttribute(gemm_mma<2>, cudaFuncAttributeMaxDynamicSharedMemorySize, GT_SMEM);
    cudaFuncSetAttribute(gemm_mma<3>, cudaFuncAttributeMaxDynamicSharedMemorySize, GT_SMEM);

    convert_all<<<dim3(8192, 5), 256>>>(hidden, q_w, k_w, v_w, o_w);
    gemm_mma<1><<<dim3(16, 32, 3), 256, GT_SMEM>>>(nullptr);
    rope_kernel<<<32768, 256>>>();
    abar_cam_v<<<32, 256>>>();
    convert_qk<<<dim3(8192, 2), 256>>>();
    convert_vt<<<dim3(64, 32), 256>>>();
    gemm_mma<2><<<dim3(136, 32), 256, GT_SMEM>>>(nullptr);
    softmax_rows<<<65536, 128>>>();
    gemm_mma<3><<<dim3(16, 32), 256, GT_SMEM>>>(nullptr);
    convert_ao<<<8192, 256>>>();
    gemm_mma<0><<<dim3(16, 32), 256, GT_SMEM>>>(out);
}

// round 8
// speedup vs baseline: 2.2851x; 1.1192x over previous
#include <cuda_runtime.h>
#include <cuda_bf16.h>
#include <cuda_fp16.h>
#include <math.h>
#include <stdint.h>
#include <float.h>

#define B_  2
#define T_  2048
#define HID_ 2048
#define H_  16
#define D_  128
#define BH_ (B_*H_)
#define BT_ (B_*T_)
#define TT_ 4194304   // T*T

// ---------------- device scratch ----------------
__device__ float g_Q[(size_t)BH_ * T_ * D_];
__device__ float g_K[(size_t)BH_ * T_ * D_];
__device__ float g_V[(size_t)BH_ * T_ * D_];
__device__ float g_AO[(size_t)BT_ * HID_];
__device__ float g_S[(size_t)BH_ * TT_];
__device__ float g_ve[BH_ * D_];

// bf16 split operands (projections, QK^T)
__device__ __align__(16) __nv_bfloat16 g_Hh[(size_t)BT_ * HID_];
__device__ __align__(16) __nv_bfloat16 g_Hl[(size_t)BT_ * HID_];
__device__ __align__(16) __nv_bfloat16 g_Wh[3][(size_t)HID_ * HID_];
__device__ __align__(16) __nv_bfloat16 g_Wl[3][(size_t)HID_ * HID_];
__device__ __align__(16) __nv_bfloat16 g_OWh[(size_t)HID_ * HID_];
__device__ __align__(16) __nv_bfloat16 g_OWl[(size_t)HID_ * HID_];
__device__ __align__(16) __nv_bfloat16 g_AOh[(size_t)BT_ * HID_];
__device__ __align__(16) __nv_bfloat16 g_AOl[(size_t)BT_ * HID_];
__device__ __align__(16) __nv_bfloat16 g_Qh[(size_t)BH_ * T_ * D_];
__device__ __align__(16) __nv_bfloat16 g_Ql[(size_t)BH_ * T_ * D_];
__device__ __align__(16) __nv_bfloat16 g_Kh[(size_t)BH_ * T_ * D_];
__device__ __align__(16) __nv_bfloat16 g_Kl[(size_t)BH_ * T_ * D_];
// fp16 single-plane operands (PV)
__device__ __align__(16) __half g_Vth[(size_t)BH_ * D_ * T_];  // [bh][d][k]
__device__ __align__(16) __half g_Ph[(size_t)BH_ * TT_];       // probs fp16

// ---------------- PTX helpers (compute_103-safe) ----------------
__device__ __forceinline__ uint32_t smem_u32(const void* p) {
    uint32_t a;
    asm("{ .reg .u64 t; cvta.to.shared.u64 t, %1; cvt.u32.u64 %0, t; }" : "=r"(a) : "l"(p));
    return a;
}
__device__ __forceinline__ void cp_async16(uint32_t dst, const void* src) {
    asm volatile("cp.async.cg.shared.global [%0], [%1], 16;" :: "r"(dst), "l"(src));
}
#define CP_COMMIT() asm volatile("cp.async.commit_group;" ::: "memory")
#define CP_WAIT(N)  asm volatile("cp.async.wait_group %0;" :: "n"(N) : "memory")

#define LDSM_X4(r, addr) \
    asm volatile("ldmatrix.sync.aligned.m8n8.x4.shared.b16 {%0,%1,%2,%3}, [%4];" \
        : "=r"((r)[0]), "=r"((r)[1]), "=r"((r)[2]), "=r"((r)[3]) : "r"(addr))

__device__ __forceinline__ void mma16816_bf(float* c, const uint32_t* a, const uint32_t* b) {
    asm volatile("mma.sync.aligned.m16n8k16.row.col.f32.bf16.bf16.f32 "
        "{%0,%1,%2,%3}, {%4,%5,%6,%7}, {%8,%9}, {%0,%1,%2,%3};"
        : "+f"(c[0]), "+f"(c[1]), "+f"(c[2]), "+f"(c[3])
        : "r"(a[0]), "r"(a[1]), "r"(a[2]), "r"(a[3]), "r"(b[0]), "r"(b[1]));
}
__device__ __forceinline__ void mma16816_fp(float* c, const uint32_t* a, const uint32_t* b) {
    asm volatile("mma.sync.aligned.m16n8k16.row.col.f32.f16.f16.f32 "
        "{%0,%1,%2,%3}, {%4,%5,%6,%7}, {%8,%9}, {%0,%1,%2,%3};"
        : "+f"(c[0]), "+f"(c[1]), "+f"(c[2]), "+f"(c[3])
        : "r"(a[0]), "r"(a[1]), "r"(a[2]), "r"(a[3]), "r"(b[0]), "r"(b[1]));
}

__device__ __forceinline__ void split2(float x, __nv_bfloat16& h, __nv_bfloat16& l) {
    h = __float2bfloat16(x);
    l = __float2bfloat16(x - __bfloat162float(h));
}

// ---------------- merged fp32 -> bf16 hi/lo split for inputs ----------------
__global__ void convert_all(const float* __restrict__ hs,
                            const float* __restrict__ qw, const float* __restrict__ kw,
                            const float* __restrict__ vw, const float* __restrict__ ow)
{
    const int sel = blockIdx.y;
    if (sel > 0 && blockIdx.x >= 4096) return;
    const size_t i = ((size_t)blockIdx.x * blockDim.x + threadIdx.x) * 4;
    const float* s;
    __nv_bfloat16 *hi, *lo;
    switch (sel) {
        case 0: s = hs; hi = g_Hh;    lo = g_Hl;    break;
        case 1: s = qw; hi = g_Wh[0]; lo = g_Wl[0]; break;
        case 2: s = kw; hi = g_Wh[1]; lo = g_Wl[1]; break;
        case 3: s = vw; hi = g_Wh[2]; lo = g_Wl[2]; break;
        default: s = ow; hi = g_OWh;  lo = g_OWl;   break;
    }
    const float4 v = *(const float4*)(s + i);
    __nv_bfloat16 h0,h1,h2,h3,l0,l1,l2,l3;
    split2(v.x,h0,l0); split2(v.y,h1,l1); split2(v.z,h2,l2); split2(v.w,h3,l3);
    *(__nv_bfloat162*)(hi + i)     = __nv_bfloat162(h0, h1);
    *(__nv_bfloat162*)(hi + i + 2) = __nv_bfloat162(h2, h3);
    *(__nv_bfloat162*)(lo + i)     = __nv_bfloat162(l0, l1);
    *(__nv_bfloat162*)(lo + i + 2) = __nv_bfloat162(l2, l3);
}

__global__ void convert_ao()
{
    const size_t i = ((size_t)blockIdx.x * blockDim.x + threadIdx.x) * 4;
    const float4 v = *(const float4*)(g_AO + i);
    __nv_bfloat16 h0,h1,h2,h3,l0,l1,l2,l3;
    split2(v.x,h0,l0); split2(v.y,h1,l1); split2(v.z,h2,l2); split2(v.w,h3,l3);
    *(__nv_bfloat162*)(g_AOh + i)     = __nv_bfloat162(h0, h1);
    *(__nv_bfloat162*)(g_AOh + i + 2) = __nv_bfloat162(h2, h3);
    *(__nv_bfloat162*)(g_AOl + i)     = __nv_bfloat162(l0, l1);
    *(__nv_bfloat162*)(g_AOl + i + 2) = __nv_bfloat162(l2, l3);
}

// ---------------- RoPE in place on Q and K + direct bf16 split emit ----------------
__global__ void rope_kernel()
{
    const int idx = blockIdx.x * blockDim.x + threadIdx.x;
    const int per = BH_ * T_ * 64;
    const bool isK = (idx >= per);
    float* P = isK ? g_K : g_Q;
    __nv_bfloat16* Oh = isK ? g_Kh : g_Qh;
    __nv_bfloat16* Ol = isK ? g_Kl : g_Ql;
    const int i = isK ? idx - per : idx;
    const int j = i & 63;
    const int bht = i >> 6;
    const int t = bht & (T_ - 1);
    const float inv = powf(10000.f, -(float)j * (1.f / 64.f));
    float s, c;
    sincosf((float)t * inv, &s, &c);
    float* row = P + (size_t)bht * 128;
    const float x1 = row[j];
    const float x2 = row[j + 64];
    const float y1 = x1 * c - x2 * s;
    const float y2 = x2 * c + x1 * s;
    row[j]      = y1;
    row[j + 64] = y2;
    __nv_bfloat16 h, l;
    split2(y1, h, l);
    Oh[(size_t)bht * 128 + j] = h;      Ol[(size_t)bht * 128 + j] = l;
    split2(y2, h, l);
    Oh[(size_t)bht * 128 + j + 64] = h; Ol[(size_t)bht * 128 + j + 64] = l;
}

// V (post-update) -> transposed fp16: Vt[bh][d][k]
__global__ void __launch_bounds__(256) convert_vt()
{
    __shared__ float tile[64][65];
    const int bh = blockIdx.y;
    const int kt = blockIdx.x >> 1;
    const int dt = blockIdx.x & 1;
    const int k0 = kt * 64, d0 = dt * 64;
    const int tid = threadIdx.x;

    for (int idx = tid; idx < 64 * 64; idx += 256) {
        const int i = idx >> 6, j = idx & 63;
        tile[i][j] = g_V[((size_t)bh * T_ + k0 + i) * 128 + d0 + j];
    }
    __syncthreads();
    for (int idx = tid; idx < 64 * 64; idx += 256) {
        const int j = idx >> 6, i = idx & 63;
        g_Vth[((size_t)bh * D_ + d0 + j) * T_ + k0 + i] = __float2half_rn(tile[i][j]);
    }
}

// ---------------- unified mma.sync GEMM ----------------
// MODE 1: QKV proj  grid(48,32): x=(w*16+n)   bf16 3-term -> g_Q/g_K/g_V [b,h,t,d]
// MODE 0: O proj    grid(16,32)               bf16 3-term -> C (d_out)
// MODE 2: S = Q K^T grid(136,32)              bf16 3-term -> g_S lower tiles
// MODE 3: AO = P V  grid(16,32)               fp16 1-term -> g_AO
#define GT_TILE  16384

template<int MODE>
__global__ void __launch_bounds__(256) gemm_mma(float* __restrict__ C)
{
    constexpr int NT = (MODE == 3) ? 2 : 4;          // tiles per stage
    constexpr uint32_t STAGE = NT * GT_TILE;
    constexpr uint32_t BOFS = (NT / 2) * GT_TILE;    // B_hi smem offset
    constexpr int TPP = 256 / NT;                    // threads per part
    constexpr int RPT = 128 / TPP;                   // rows per thread

    extern __shared__ char smem[];
    const uint32_t sbase = smem_u32(smem);
    const int tid = threadIdx.x;
    const int wid = tid >> 5;
    const int lane = tid & 31;

    int mloc, nloc, bh = 0, kchunks, arowbase, browbase, astr, bstr, wsel = 0, hsel = 0;
    const char *pA0, *pA1 = nullptr, *pB0, *pB1 = nullptr;

    if (MODE == 1) {
        wsel = blockIdx.x >> 4;
        hsel = blockIdx.x & 15;
        mloc = blockIdx.y * 128; nloc = hsel * 128;
        arowbase = mloc; browbase = nloc; astr = 2048; bstr = 2048; kchunks = 32;
        pA0 = (const char*)g_Hh; pA1 = (const char*)g_Hl;
        pB0 = (const char*)g_Wh[wsel]; pB1 = (const char*)g_Wl[wsel];
    } else if (MODE == 0) {
        mloc = blockIdx.y * 128; nloc = blockIdx.x * 128;
        arowbase = mloc; browbase = nloc; astr = 2048; bstr = 2048; kchunks = 32;
        pA0 = (const char*)g_AOh; pA1 = (const char*)g_AOl;
        pB0 = (const char*)g_OWh; pB1 = (const char*)g_OWl;
    } else if (MODE == 2) {
        bh = blockIdx.y;
        const int x = blockIdx.x;
        int i = (int)((sqrtf(8.f * x + 1.f) - 1.f) * 0.5f);
        while ((i + 1) * (i + 2) / 2 <= x) ++i;
        while (i * (i + 1) / 2 > x) --i;
        const int j = x - i * (i + 1) / 2;
        mloc = i * 128; nloc = j * 128;
        arowbase = bh * 2048 + mloc; browbase = bh * 2048 + nloc;
        astr = 128; bstr = 128; kchunks = 2;
        pA0 = (const char*)g_Qh; pA1 = (const char*)g_Ql;
        pB0 = (const char*)g_Kh; pB1 = (const char*)g_Kl;
    } else {
        bh = blockIdx.y;
        mloc = blockIdx.x * 128; nloc = 0;
        arowbase = bh * 2048 + mloc; browbase = bh * 128;
        astr = 2048; bstr = 2048; kchunks = 2 * (blockIdx.x + 1);
        pA0 = (const char*)g_Ph; pB0 = (const char*)g_Vth;
    }

    const int part = tid / TPP;
    const int u = tid % TPP;
    const char* gsrc;
    if (MODE == 3) gsrc = (part == 0) ? pA0 : pB0;
    else gsrc = (part == 0) ? pA0 : (part == 1) ? pA1 : (part == 2) ? pB0 : pB1;
    const bool isA = (part < NT / 2);
    const int growbase = isA ? arowbase : browbase;
    const int gstride  = isA ? astr : bstr;
    const uint32_t tpart = sbase + part * GT_TILE;

    auto load_stage = [&](int c, int s) {
#pragma unroll
        for (int rr = 0; rr < RPT; rr++) {
            const int r = u * RPT + rr;
            const char* src = gsrc + ((size_t)(growbase + r) * gstride + c * 64) * 2;
            const uint32_t drow = tpart + s * STAGE + r * 128;
#pragma unroll
            for (int g = 0; g < 8; g++)
                cp_async16(drow + (((g ^ (r & 7)) << 4)), src + g * 16);
        }
    };

    const int wm = wid & 3;
    const int wn = wid >> 2;

    float acc[2][8][4];
#pragma unroll
    for (int a = 0; a < 2; a++)
#pragma unroll
        for (int b = 0; b < 8; b++)
#pragma unroll
            for (int cx = 0; cx < 4; cx++) acc[a][b][cx] = 0.f;

    load_stage(0, 0);
    CP_COMMIT();

    for (int c = 0; c < kchunks; ++c) {
        const int s = c & 1;
        if (c + 1 < kchunks) {
            load_stage(c + 1, s ^ 1);
            CP_COMMIT();
            CP_WAIT(1);
        } else {
            CP_WAIT(0);
        }
        __syncthreads();

        const uint32_t st = sbase + s * STAGE;
#pragma unroll
        for (int ks = 0; ks < 4; ks++) {
            const int lr = lane & 15;
            const int g = ks * 2 + (lane >> 4);

            uint32_t ah[2][4], al[2][4];
#pragma unroll
            for (int mb = 0; mb < 2; mb++) {
                const int r = wm * 32 + mb * 16 + lr;
                const uint32_t off = r * 128 + (((g ^ (r & 7)) << 4));
                LDSM_X4(ah[mb], st + off);
                if (MODE != 3) LDSM_X4(al[mb], st + GT_TILE + off);
            }
            uint32_t bhf[8][2], blf[8][2];
#pragma unroll
            for (int np = 0; np < 4; np++) {
                const int r = wn * 64 + np * 16 + lr;
                const uint32_t off = r * 128 + (((g ^ (r & 7)) << 4));
                uint32_t t4[4];
                LDSM_X4(t4, st + BOFS + off);
                bhf[2*np][0] = t4[0]; bhf[2*np][1] = t4[2];
                bhf[2*np+1][0] = t4[1]; bhf[2*np+1][1] = t4[3];
                if (MODE != 3) {
                    LDSM_X4(t4, st + BOFS + GT_TILE + off);
                    blf[2*np][0] = t4[0]; blf[2*np][1] = t4[2];
                    blf[2*np+1][0] = t4[1]; blf[2*np+1][1] = t4[3];
                }
            }
#pragma unroll
            for (int mb = 0; mb < 2; mb++)
#pragma unroll
                for (int nb = 0; nb < 8; nb++) {
                    if (MODE == 3) {
                        mma16816_fp(acc[mb][nb], ah[mb], bhf[nb]);
                    } else {
                        mma16816_bf(acc[mb][nb], ah[mb], bhf[nb]);
                        mma16816_bf(acc[mb][nb], ah[mb], blf[nb]);
                        mma16816_bf(acc[mb][nb], al[mb], bhf[nb]);
                    }
                }
        }
        __syncthreads();
    }

    // epilogue
#pragma unroll
    for (int mb = 0; mb < 2; mb++)
#pragma unroll
        for (int rh = 0; rh < 2; rh++) {
            const int row = wm * 32 + mb * 16 + rh * 8 + (lane >> 2);
            float* dst;
            if (MODE == 1) {
                const int gr = mloc + row;
                const int bb = gr >> 11, t = gr & 2047;
                float* G = (wsel == 0) ? g_Q : (wsel == 1) ? g_K : g_V;
                dst = G + (((size_t)(bb * H_ + hsel) * T_ + t) << 7);
            } else if (MODE == 0) {
                dst = C + (size_t)(mloc + row) * 2048 + nloc;
            } else if (MODE == 2) {
                dst = g_S + (size_t)bh * TT_ + (size_t)(mloc + row) * 2048 + nloc;
            } else {
                const int t = mloc + row;
                const int bb = bh >> 4, h = bh & 15;
                dst = g_AO + ((size_t)(bb * T_ + t)) * 2048 + h * 128;
            }
            const int cbase = wn * 64 + (lane & 3) * 2;
#pragma unroll
            for (int nb = 0; nb < 8; nb++)
                *(float2*)(dst + cbase + nb * 8) =
                    make_float2(acc[mb][nb][rh * 2], acc[mb][nb][rh * 2 + 1]);
        }
}

// ---------------- A_bar softmax + CAM bernoulli -> g_ve ----------------
__device__ __forceinline__ uint32_t rotl32(uint32_t x, int r) { return (x << r) | (x >> (32 - r)); }

__global__ void __launch_bounds__(256) abar_cam()
{
    const int bh = blockIdx.x;
    __shared__ float qrow[128];
    __shared__ float sc[2048];
    __shared__ float red[256];
    __shared__ float maskf;
    const int tid = threadIdx.x;

    const float* Qr = g_Q + ((size_t)bh * T_ + (T_ - 1)) * 128;
    if (tid < 128) qrow[tid] = Qr[tid];
    __syncthreads();

    for (int k = tid; k < 2048; k += 256) {
        const float4* kr = (const float4*)(g_K + ((size_t)bh * T_ + k) * 128);
        const float4* qr = (const float4*)qrow;
        float s = 0.f;
#pragma unroll
        for (int i = 0; i < 32; i++) {
            const float4 kv = kr[i], qv = qr[i];
            s = fmaf(kv.x, qv.x, s); s = fmaf(kv.y, qv.y, s);
            s = fmaf(kv.z, qv.z, s); s = fmaf(kv.w, qv.w, s);
        }
        sc[k] = s * 0.08838834764831845f;
    }
    __syncthreads();

    float m = -FLT_MAX;
    for (int k = tid; k < 2048; k += 256) m = fmaxf(m, sc[k]);
    red[tid] = m; __syncthreads();
    for (int o = 128; o > 0; o >>= 1) { if (tid < o) red[tid] = fmaxf(red[tid], red[tid + o]); __syncthreads(); }
    const float gm = red[0];
    __syncthreads();

    float sum = 0.f;
    for (int k = tid; k < 2048; k += 256) { const float p = expf(sc[k] - gm); sc[k] = p; sum += p; }
    red[tid] = sum; __syncthreads();
    for (int o = 128; o > 0; o >>= 1) { if (tid < o) red[tid] += red[tid + o]; __syncthreads(); }
    const float invs = 1.f / red[0];
    __syncthreads();

    for (int k = tid; k < 2048; k += 256) sc[k] *= invs;
    __syncthreads();

    float ws = 0.f;
    for (int k = 1536 + tid; k < 2048; k += 256) ws += sc[k];
    red[tid] = ws; __syncthreads();
    for (int o = 128; o > 0; o >>= 1) { if (tid < o) red[tid] += red[tid + o]; __syncthreads(); }

    if (tid == 0) {
        const float avg = fmaxf(red[0] * (1.f / 512.f), 1e-6f);
        float p = fminf(fmaxf(sc[1535] / avg, 0.f), 1.f);
        uint32_t x0 = 0u, x1 = (uint32_t)bh;
        const uint32_t k0 = 0u, k1 = 42u, k2 = 0x1BD11BDAu ^ k0 ^ k1;
        x0 += k0; x1 += k1;
#define TF4(a,b,c,d)  x0+=x1; x1=rotl32(x1,a); x1^=x0; \
                      x0+=x1; x1=rotl32(x1,b); x1^=x0; \
                      x0+=x1; x1=rotl32(x1,c); x1^=x0; \
                      x0+=x1; x1=rotl32(x1,d); x1^=x0;
        TF4(13,15,26,6)   x0 += k1; x1 += k2 + 1u;
        TF4(17,29,16,24)  x0 += k2; x1 += k0 + 2u;
        TF4(13,15,26,6)   x0 += k0; x1 += k1 + 3u;
        TF4(17,29,16,24)  x0 += k1; x1 += k2 + 4u;
        TF4(13,15,26,6)   x0 += k2; x1 += k0 + 5u;
#undef TF4
        const uint32_t bits = x0 ^ x1;
        float uu = __uint_as_float((bits >> 9) | 0x3f800000u) - 1.0f;
        uu = fmaxf(uu, 0.f);
        maskf = (uu < p) ? 1.f : 0.f;
    }
    __syncthreads();

    if (tid < 128)
        g_ve[bh * 128 + tid] = g_V[((size_t)bh * T_ + 1535) * 128 + tid] * maskf * (1.f / 512.f);
}

__global__ void v_update_kernel()
{
    const int idx = blockIdx.x * blockDim.x + threadIdx.x;
    const int bh = idx >> 16;
    const int rest = idx & 65535;
    const int r = rest >> 7;
    const int d = rest & 127;
    g_V[((size_t)bh * T_ + 1536 + r) * 128 + d] += g_ve[(bh << 7) + d];
}

// ---------------- row softmax: S -> fp16 P (zero-padded to tile) ----------------
__global__ void __launch_bounds__(128) softmax_rows()
{
    const int gid = blockIdx.x;
    const int bh = gid >> 11;
    const int t = gid & 2047;
    const int n = t + 1;
    const int padend = ((t >> 7) + 1) << 7;
    const float* srow = g_S + (size_t)bh * TT_ + (size_t)t * 2048;
    __half* ph = g_Ph + (size_t)bh * TT_ + (size_t)t * 2048;

    __shared__ float e[2048];
    __shared__ float red[4];
    const int tid = threadIdx.x;
    const int wid = tid >> 5, lane = tid & 31;
    const float scale = 0.08838834764831845f;

    float m = -FLT_MAX;
    for (int k = tid; k < n; k += 128) {
        const float v = srow[k] * scale;
        e[k] = v;
        m = fmaxf(m, v);
    }
#pragma unroll
    for (int o = 16; o > 0; o >>= 1) m = fmaxf(m, __shfl_xor_sync(0xffffffffu, m, o));
    if (lane == 0) red[wid] = m;
    __syncthreads();
    m = fmaxf(fmaxf(red[0], red[1]), fmaxf(red[2], red[3]));
    __syncthreads();

    float sum = 0.f;
    for (int k = tid; k < n; k += 128) {
        const float p = expf(e[k] - m);
        e[k] = p;
        sum += p;
    }
#pragma unroll
    for (int o = 16; o > 0; o >>= 1) sum += __shfl_xor_sync(0xffffffffu, sum, o);
    if (lane == 0) red[wid] = sum;
    __syncthreads();
    const float inv = 1.f / (red[0] + red[1] + red[2] + red[3]);

    for (int k = tid; k < padend; k += 128)
        ph[k] = __float2half_rn(k < n ? e[k] * inv : 0.f);
}

// ---------------- launch ----------------
extern "C" void kernel_launch(void* const* d_in, const int* in_sizes, int n_in,
                              void* d_out, int out_size)
{
    (void)in_sizes; (void)n_in; (void)out_size;
    const float* hidden = (const float*)d_in[0];
    const float* q_w = (const float*)d_in[2];
    const float* k_w = (const float*)d_in[3];
    const float* v_w = (const float*)d_in[4];
    const float* o_w = (const float*)d_in[5];
    float* out = (float*)d_out;

    cudaFuncSetAttribute(gemm_mma<0>, cudaFuncAttributeMaxDynamicSharedMemorySize, 131072);
    cudaFuncSetAttribute(gemm_mma<1>, cudaFuncAttributeMaxDynamicSharedMemorySize, 131072);
    cudaFuncSetAttribute(gemm_mma<2>, cudaFuncAttributeMaxDynamicSharedMemorySize, 131072);
    cudaFuncSetAttribute(gemm_mma<3>, cudaFuncAttributeMaxDynamicSharedMemorySize, 65536);

    convert_all<<<dim3(8192, 5), 256>>>(hidden, q_w, k_w, v_w, o_w);
    gemm_mma<1><<<dim3(48, 32), 256, 131072>>>(nullptr);
    rope_kernel<<<32768, 256>>>();
    abar_cam<<<32, 256>>>();
    v_update_kernel<<<8192, 256>>>();
    convert_vt<<<dim3(64, 32), 256>>>();
    gemm_mma<2><<<dim3(136, 32), 256, 131072>>>(nullptr);
    softmax_rows<<<65536, 128>>>();
    gemm_mma<3><<<dim3(16, 32), 256, 65536>>>(nullptr);
    convert_ao<<<8192, 256>>>();
    gemm_mma<0><<<dim3(16, 32), 256, 131072>>>(out);
}

// round 9
// speedup vs baseline: 2.4552x; 1.0744x over previous
#include <cuda_runtime.h>
#include <cuda_bf16.h>
#include <cuda_fp16.h>
#include <math.h>
#include <stdint.h>
#include <float.h>

#define B_  2
#define T_  2048
#define HID_ 2048
#define H_  16
#define D_  128
#define BH_ (B_*H_)
#define BT_ (B_*T_)

// ---------------- device scratch ----------------
__device__ float g_Q[(size_t)BH_ * T_ * D_];
__device__ float g_K[(size_t)BH_ * T_ * D_];
__device__ float g_V[(size_t)BH_ * T_ * D_];
__device__ float g_AO[(size_t)BT_ * HID_];
__device__ float g_ve[BH_ * D_];

// bf16 split operands
__device__ __align__(16) __nv_bfloat16 g_Hh[(size_t)BT_ * HID_];
__device__ __align__(16) __nv_bfloat16 g_Hl[(size_t)BT_ * HID_];
__device__ __align__(16) __nv_bfloat16 g_Wh[3][(size_t)HID_ * HID_];
__device__ __align__(16) __nv_bfloat16 g_Wl[3][(size_t)HID_ * HID_];
__device__ __align__(16) __nv_bfloat16 g_OWh[(size_t)HID_ * HID_];
__device__ __align__(16) __nv_bfloat16 g_OWl[(size_t)HID_ * HID_];
__device__ __align__(16) __nv_bfloat16 g_AOh[(size_t)BT_ * HID_];
__device__ __align__(16) __nv_bfloat16 g_AOl[(size_t)BT_ * HID_];
__device__ __align__(16) __nv_bfloat16 g_Qh[(size_t)BH_ * T_ * D_];
__device__ __align__(16) __nv_bfloat16 g_Ql[(size_t)BH_ * T_ * D_];
__device__ __align__(16) __nv_bfloat16 g_Kh[(size_t)BH_ * T_ * D_];
__device__ __align__(16) __nv_bfloat16 g_Kl[(size_t)BH_ * T_ * D_];
// fp16 V transposed: Vt[bh][d][k]
__device__ __align__(16) __half g_Vth[(size_t)BH_ * D_ * T_];

// ---------------- PTX helpers (compute_103-safe) ----------------
__device__ __forceinline__ uint32_t smem_u32(const void* p) {
    uint32_t a;
    asm("{ .reg .u64 t; cvta.to.shared.u64 t, %1; cvt.u32.u64 %0, t; }" : "=r"(a) : "l"(p));
    return a;
}
__device__ __forceinline__ void cp_async16(uint32_t dst, const void* src) {
    asm volatile("cp.async.cg.shared.global [%0], [%1], 16;" :: "r"(dst), "l"(src));
}
#define CP_COMMIT() asm volatile("cp.async.commit_group;" ::: "memory")
#define CP_WAIT(N)  asm volatile("cp.async.wait_group %0;" :: "n"(N) : "memory")

#define LDSM_X4(r, addr) \
    asm volatile("ldmatrix.sync.aligned.m8n8.x4.shared.b16 {%0,%1,%2,%3}, [%4];" \
        : "=r"((r)[0]), "=r"((r)[1]), "=r"((r)[2]), "=r"((r)[3]) : "r"(addr))

__device__ __forceinline__ void mma16816_bf(float* c, const uint32_t* a, const uint32_t* b) {
    asm volatile("mma.sync.aligned.m16n8k16.row.col.f32.bf16.bf16.f32 "
        "{%0,%1,%2,%3}, {%4,%5,%6,%7}, {%8,%9}, {%0,%1,%2,%3};"
        : "+f"(c[0]), "+f"(c[1]), "+f"(c[2]), "+f"(c[3])
        : "r"(a[0]), "r"(a[1]), "r"(a[2]), "r"(a[3]), "r"(b[0]), "r"(b[1]));
}
__device__ __forceinline__ void mma16816_fp(float* c, const uint32_t* a, const uint32_t* b) {
    asm volatile("mma.sync.aligned.m16n8k16.row.col.f32.f16.f16.f32 "
        "{%0,%1,%2,%3}, {%4,%5,%6,%7}, {%8,%9}, {%0,%1,%2,%3};"
        : "+f"(c[0]), "+f"(c[1]), "+f"(c[2]), "+f"(c[3])
        : "r"(a[0]), "r"(a[1]), "r"(a[2]), "r"(a[3]), "r"(b[0]), "r"(b[1]));
}

__device__ __forceinline__ void split2(float x, __nv_bfloat16& h, __nv_bfloat16& l) {
    h = __float2bfloat16(x);
    l = __float2bfloat16(x - __bfloat162float(h));
}
__device__ __forceinline__ uint32_t packh2(float a, float b) {
    __half2 h = __floats2half2_rn(a, b);
    return *reinterpret_cast<uint32_t*>(&h);
}

// ---------------- merged fp32 -> bf16 hi/lo split for inputs ----------------
__global__ void convert_all(const float* __restrict__ hs,
                            const float* __restrict__ qw, const float* __restrict__ kw,
                            const float* __restrict__ vw, const float* __restrict__ ow)
{
    const int sel = blockIdx.y;
    if (sel > 0 && blockIdx.x >= 4096) return;
    const size_t i = ((size_t)blockIdx.x * blockDim.x + threadIdx.x) * 4;
    const float* s;
    __nv_bfloat16 *hi, *lo;
    switch (sel) {
        case 0: s = hs; hi = g_Hh;    lo = g_Hl;    break;
        case 1: s = qw; hi = g_Wh[0]; lo = g_Wl[0]; break;
        case 2: s = kw; hi = g_Wh[1]; lo = g_Wl[1]; break;
        case 3: s = vw; hi = g_Wh[2]; lo = g_Wl[2]; break;
        default: s = ow; hi = g_OWh;  lo = g_OWl;   break;
    }
    const float4 v = *(const float4*)(s + i);
    __nv_bfloat16 h0,h1,h2,h3,l0,l1,l2,l3;
    split2(v.x,h0,l0); split2(v.y,h1,l1); split2(v.z,h2,l2); split2(v.w,h3,l3);
    *(__nv_bfloat162*)(hi + i)     = __nv_bfloat162(h0, h1);
    *(__nv_bfloat162*)(hi + i + 2) = __nv_bfloat162(h2, h3);
    *(__nv_bfloat162*)(lo + i)     = __nv_bfloat162(l0, l1);
    *(__nv_bfloat162*)(lo + i + 2) = __nv_bfloat162(l2, l3);
}

__global__ void convert_ao()
{
    const size_t i = ((size_t)blockIdx.x * blockDim.x + threadIdx.x) * 4;
    const float4 v = *(const float4*)(g_AO + i);
    __nv_bfloat16 h0,h1,h2,h3,l0,l1,l2,l3;
    split2(v.x,h0,l0); split2(v.y,h1,l1); split2(v.z,h2,l2); split2(v.w,h3,l3);
    *(__nv_bfloat162*)(g_AOh + i)     = __nv_bfloat162(h0, h1);
    *(__nv_bfloat162*)(g_AOh + i + 2) = __nv_bfloat162(h2, h3);
    *(__nv_bfloat162*)(g_AOl + i)     = __nv_bfloat162(l0, l1);
    *(__nv_bfloat162*)(g_AOl + i + 2) = __nv_bfloat162(l2, l3);
}

// ---------------- RoPE in place on Q and K + direct bf16 split emit ----------------
__global__ void rope_kernel()
{
    const int idx = blockIdx.x * blockDim.x + threadIdx.x;
    const int per = BH_ * T_ * 64;
    const bool isK = (idx >= per);
    float* P = isK ? g_K : g_Q;
    __nv_bfloat16* Oh = isK ? g_Kh : g_Qh;
    __nv_bfloat16* Ol = isK ? g_Kl : g_Ql;
    const int i = isK ? idx - per : idx;
    const int j = i & 63;
    const int bht = i >> 6;
    const int t = bht & (T_ - 1);
    const float inv = powf(10000.f, -(float)j * (1.f / 64.f));
    float s, c;
    sincosf((float)t * inv, &s, &c);
    float* row = P + (size_t)bht * 128;
    const float x1 = row[j];
    const float x2 = row[j + 64];
    const float y1 = x1 * c - x2 * s;
    const float y2 = x2 * c + x1 * s;
    row[j]      = y1;
    row[j + 64] = y2;
    __nv_bfloat16 h, l;
    split2(y1, h, l);
    Oh[(size_t)bht * 128 + j] = h;      Ol[(size_t)bht * 128 + j] = l;
    split2(y2, h, l);
    Oh[(size_t)bht * 128 + j + 64] = h; Ol[(size_t)bht * 128 + j + 64] = l;
}

// ---------------- A_bar softmax + CAM bernoulli -> g_ve ----------------
__device__ __forceinline__ uint32_t rotl32(uint32_t x, int r) { return (x << r) | (x >> (32 - r)); }

__global__ void __launch_bounds__(256) abar_cam()
{
    const int bh = blockIdx.x;
    __shared__ float qrow[128];
    __shared__ float sc[2048];
    __shared__ float red[256];
    __shared__ float maskf;
    const int tid = threadIdx.x;

    const float* Qr = g_Q + ((size_t)bh * T_ + (T_ - 1)) * 128;
    if (tid < 128) qrow[tid] = Qr[tid];
    __syncthreads();

    for (int k = tid; k < 2048; k += 256) {
        const float4* kr = (const float4*)(g_K + ((size_t)bh * T_ + k) * 128);
        const float4* qr = (const float4*)qrow;
        float s = 0.f;
#pragma unroll
        for (int i = 0; i < 32; i++) {
            const float4 kv = kr[i], qv = qr[i];
            s = fmaf(kv.x, qv.x, s); s = fmaf(kv.y, qv.y, s);
            s = fmaf(kv.z, qv.z, s); s = fmaf(kv.w, qv.w, s);
        }
        sc[k] = s * 0.08838834764831845f;
    }
    __syncthreads();

    float m = -FLT_MAX;
    for (int k = tid; k < 2048; k += 256) m = fmaxf(m, sc[k]);
    red[tid] = m; __syncthreads();
    for (int o = 128; o > 0; o >>= 1) { if (tid < o) red[tid] = fmaxf(red[tid], red[tid + o]); __syncthreads(); }
    const float gm = red[0];
    __syncthreads();

    float sum = 0.f;
    for (int k = tid; k < 2048; k += 256) { const float p = expf(sc[k] - gm); sc[k] = p; sum += p; }
    red[tid] = sum; __syncthreads();
    for (int o = 128; o > 0; o >>= 1) { if (tid < o) red[tid] += red[tid + o]; __syncthreads(); }
    const float invs = 1.f / red[0];
    __syncthreads();

    for (int k = tid; k < 2048; k += 256) sc[k] *= invs;
    __syncthreads();

    float ws = 0.f;
    for (int k = 1536 + tid; k < 2048; k += 256) ws += sc[k];
    red[tid] = ws; __syncthreads();
    for (int o = 128; o > 0; o >>= 1) { if (tid < o) red[tid] += red[tid + o]; __syncthreads(); }

    if (tid == 0) {
        const float avg = fmaxf(red[0] * (1.f / 512.f), 1e-6f);
        float p = fminf(fmaxf(sc[1535] / avg, 0.f), 1.f);
        uint32_t x0 = 0u, x1 = (uint32_t)bh;
        const uint32_t k0 = 0u, k1 = 42u, k2 = 0x1BD11BDAu ^ k0 ^ k1;
        x0 += k0; x1 += k1;
#define TF4(a,b,c,d)  x0+=x1; x1=rotl32(x1,a); x1^=x0; \
                      x0+=x1; x1=rotl32(x1,b); x1^=x0; \
                      x0+=x1; x1=rotl32(x1,c); x1^=x0; \
                      x0+=x1; x1=rotl32(x1,d); x1^=x0;
        TF4(13,15,26,6)   x0 += k1; x1 += k2 + 1u;
        TF4(17,29,16,24)  x0 += k2; x1 += k0 + 2u;
        TF4(13,15,26,6)   x0 += k0; x1 += k1 + 3u;
        TF4(17,29,16,24)  x0 += k1; x1 += k2 + 4u;
        TF4(13,15,26,6)   x0 += k2; x1 += k0 + 5u;
#undef TF4
        const uint32_t bits = x0 ^ x1;
        float uu = __uint_as_float((bits >> 9) | 0x3f800000u) - 1.0f;
        uu = fmaxf(uu, 0.f);
        maskf = (uu < p) ? 1.f : 0.f;
    }
    __syncthreads();

    if (tid < 128)
        g_ve[bh * 128 + tid] = g_V[((size_t)bh * T_ + 1535) * 128 + tid] * maskf * (1.f / 512.f);
}

// V -> transposed fp16 Vt[bh][d][k], with fused CAM window update (+v_e for k>=1536)
__global__ void __launch_bounds__(256) convert_vt()
{
    __shared__ float tile[64][65];
    const int bh = blockIdx.y;
    const int kt = blockIdx.x >> 1;
    const int dt = blockIdx.x & 1;
    const int k0 = kt * 64, d0 = dt * 64;
    const int tid = threadIdx.x;

    for (int idx = tid; idx < 64 * 64; idx += 256) {
        const int i = idx >> 6, j = idx & 63;
        tile[i][j] = g_V[((size_t)bh * T_ + k0 + i) * 128 + d0 + j];
    }
    __syncthreads();
    for (int idx = tid; idx < 64 * 64; idx += 256) {
        const int j = idx >> 6, i = idx & 63;
        float x = tile[i][j];
        if (k0 + i >= 1536) x += g_ve[bh * 128 + d0 + j];
        g_Vth[((size_t)bh * D_ + d0 + j) * T_ + k0 + i] = __float2half_rn(x);
    }
}

// ---------------- mma.sync split-bf16 GEMM (projections) ----------------
// MODE 1: QKV proj grid(48,32): x=(w*16+n)  -> g_Q/g_K/g_V [b,h,t,d]
// MODE 0: O proj   grid(16,32)              -> C (d_out)
#define GT_TILE  16384

template<int MODE>
__global__ void __launch_bounds__(256) gemm_mma(float* __restrict__ C)
{
    extern __shared__ char smem[];
    const uint32_t sbase = smem_u32(smem);
    const int tid = threadIdx.x;
    const int wid = tid >> 5;
    const int lane = tid & 31;

    int wsel = 0, hsel = 0, mloc, nloc;
    const __nv_bfloat16 *pA0, *pA1, *pB0, *pB1;
    if (MODE == 1) {
        wsel = blockIdx.x >> 4;
        hsel = blockIdx.x & 15;
        mloc = blockIdx.y * 128; nloc = hsel * 128;
        pA0 = g_Hh; pA1 = g_Hl; pB0 = g_Wh[wsel]; pB1 = g_Wl[wsel];
    } else {
        mloc = blockIdx.y * 128; nloc = blockIdx.x * 128;
        pA0 = g_AOh; pA1 = g_AOl; pB0 = g_OWh; pB1 = g_OWl;
    }

    const int part = tid >> 6;
    const int u = tid & 63;
    const __nv_bfloat16* gsrc = (part == 0) ? pA0 : (part == 1) ? pA1 : (part == 2) ? pB0 : pB1;
    const int growbase = (part < 2) ? mloc : nloc;
    const uint32_t tpart = sbase + part * GT_TILE;

    auto load_stage = [&](int c, int s) {
#pragma unroll
        for (int rr = 0; rr < 2; rr++) {
            const int r = u * 2 + rr;
            const __nv_bfloat16* src = gsrc + (size_t)(growbase + r) * 2048 + c * 64;
            const uint32_t drow = tpart + s * (4 * GT_TILE) + r * 128;
#pragma unroll
            for (int g = 0; g < 8; g++)
                cp_async16(drow + (((g ^ (r & 7)) << 4)), src + g * 8);
        }
    };

    const int wm = wid & 3;
    const int wn = wid >> 2;

    float acc[2][8][4];
#pragma unroll
    for (int a = 0; a < 2; a++)
#pragma unroll
        for (int b = 0; b < 8; b++)
#pragma unroll
            for (int cx = 0; cx < 4; cx++) acc[a][b][cx] = 0.f;

    load_stage(0, 0);
    CP_COMMIT();

    for (int c = 0; c < 32; ++c) {
        const int s = c & 1;
        if (c + 1 < 32) {
            load_stage(c + 1, s ^ 1);
            CP_COMMIT();
            CP_WAIT(1);
        } else {
            CP_WAIT(0);
        }
        __syncthreads();

        const uint32_t st = sbase + s * (4 * GT_TILE);
#pragma unroll
        for (int ks = 0; ks < 4; ks++) {
            const int lr = lane & 15;
            const int g = ks * 2 + (lane >> 4);

            uint32_t ah[2][4], al[2][4];
#pragma unroll
            for (int mb = 0; mb < 2; mb++) {
                const int r = wm * 32 + mb * 16 + lr;
                const uint32_t off = r * 128 + (((g ^ (r & 7)) << 4));
                LDSM_X4(ah[mb], st + off);
                LDSM_X4(al[mb], st + GT_TILE + off);
            }
            uint32_t bhf[8][2], blf[8][2];
#pragma unroll
            for (int np = 0; np < 4; np++) {
                const int r = wn * 64 + np * 16 + lr;
                const uint32_t off = r * 128 + (((g ^ (r & 7)) << 4));
                uint32_t t4[4];
                LDSM_X4(t4, st + 2 * GT_TILE + off);
                bhf[2*np][0] = t4[0]; bhf[2*np][1] = t4[2];
                bhf[2*np+1][0] = t4[1]; bhf[2*np+1][1] = t4[3];
                LDSM_X4(t4, st + 3 * GT_TILE + off);
                blf[2*np][0] = t4[0]; blf[2*np][1] = t4[2];
                blf[2*np+1][0] = t4[1]; blf[2*np+1][1] = t4[3];
            }
#pragma unroll
            for (int mb = 0; mb < 2; mb++)
#pragma unroll
                for (int nb = 0; nb < 8; nb++) {
                    mma16816_bf(acc[mb][nb], ah[mb], bhf[nb]);
                    mma16816_bf(acc[mb][nb], ah[mb], blf[nb]);
                    mma16816_bf(acc[mb][nb], al[mb], bhf[nb]);
                }
        }
        __syncthreads();
    }

#pragma unroll
    for (int mb = 0; mb < 2; mb++)
#pragma unroll
        for (int rh = 0; rh < 2; rh++) {
            const int row = wm * 32 + mb * 16 + rh * 8 + (lane >> 2);
            float* dst;
            if (MODE == 1) {
                const int gr = mloc + row;
                const int bb = gr >> 11, t = gr & 2047;
                float* G = (wsel == 0) ? g_Q : (wsel == 1) ? g_K : g_V;
                dst = G + (((size_t)(bb * H_ + hsel) * T_ + t) << 7);
            } else {
                dst = C + (size_t)(mloc + row) * 2048 + nloc;
            }
            const int cbase = wn * 64 + (lane & 3) * 2;
#pragma unroll
            for (int nb = 0; nb < 8; nb++)
                *(float2*)(dst + cbase + nb * 8) =
                    make_float2(acc[mb][nb][rh * 2], acc[mb][nb][rh * 2 + 1]);
        }
}

// ---------------- fused flash attention (mma) ----------------
// grid (16, 32): one 128-row q-tile per CTA per bh. 8 warps, warp = m16 x n128.
// smem: Q hi/lo (64KB) + K hi/lo double-buffered (128KB) + V fp16 single (32KB) = 224KB.
#define FL_SMEM 229376

__global__ void __launch_bounds__(256) flash_mma()
{
    extern __shared__ char smem[];
    const uint32_t sb = smem_u32(smem);
    const uint32_t QS = sb, KS = sb + 65536, VS = sb + 196608;
    const int tid = threadIdx.x, wid = tid >> 5, lane = tid & 31;
    const int bh = blockIdx.y;
    const int qb = 15 - blockIdx.x;       // heavy tiles first
    const int nkt = qb + 1;

    // ---- Q preload (hi/lo, 2 chunks each) ----
    {
        const int part = tid >> 6, u = tid & 63;
        const int plane = part >> 1, c = part & 1;
        const __nv_bfloat16* base = (plane ? g_Ql : g_Qh) + ((size_t)(bh * 2048 + qb * 128)) * 128 + c * 64;
        const uint32_t dstt = QS + part * 16384;
#pragma unroll
        for (int rr = 0; rr < 2; rr++) {
            const int r = u * 2 + rr;
            const char* sp = (const char*)(base + (size_t)r * 128);
            const uint32_t drow = dstt + r * 128;
#pragma unroll
            for (int g = 0; g < 8; g++) cp_async16(drow + ((g ^ (r & 7)) << 4), sp + g * 16);
        }
    }
    CP_COMMIT();

    auto loadK = [&](int j, int s) {
        const int part = tid >> 6, u = tid & 63;
        const int plane = part >> 1, c = part & 1;
        const __nv_bfloat16* base = (plane ? g_Kl : g_Kh) + ((size_t)(bh * 2048 + j * 128)) * 128 + c * 64;
        const uint32_t dstt = KS + s * 65536 + part * 16384;
#pragma unroll
        for (int rr = 0; rr < 2; rr++) {
            const int r = u * 2 + rr;
            const char* sp = (const char*)(base + (size_t)r * 128);
            const uint32_t drow = dstt + r * 128;
#pragma unroll
            for (int g = 0; g < 8; g++) cp_async16(drow + ((g ^ (r & 7)) << 4), sp + g * 16);
        }
    };
    auto loadV = [&](int j) {
        const int c = tid >> 7, r = tid & 127;
        const char* sp = (const char*)(g_Vth + ((size_t)(bh * 128 + r)) * 2048 + j * 128 + c * 64);
        const uint32_t drow = VS + c * 16384 + r * 128;
#pragma unroll
        for (int g = 0; g < 8; g++) cp_async16(drow + ((g ^ (r & 7)) << 4), sp + g * 16);
    };

    loadK(0, 0); CP_COMMIT();
    loadV(0);    CP_COMMIT();

    float oacc[16][4];
#pragma unroll
    for (int nt = 0; nt < 16; nt++)
#pragma unroll
        for (int e = 0; e < 4; e++) oacc[nt][e] = 0.f;
    float m0 = -1e30f, m1 = -1e30f, l0 = 0.f, l1 = 0.f;
    uint32_t pfrag[8][4];

    const float scale = 0.08838834764831845f;
    const int lr = lane & 15;
    const int rloc = (lane >> 2);          // row within warp m16
    const int colloc = (lane & 3) * 2;

    for (int j = 0; j < nkt; j++) {
        const int sK = j & 1;
        CP_WAIT(0);
        __syncthreads();

        // ---- S = Q K^T, 3-term bf16 ----
        float sacc[16][4];
#pragma unroll
        for (int nt = 0; nt < 16; nt++)
#pragma unroll
            for (int e = 0; e < 4; e++) sacc[nt][e] = 0.f;

        const uint32_t kst = KS + sK * 65536;
#pragma unroll
        for (int ks = 0; ks < 8; ks++) {
            const int chunk = ks >> 2;
            const int g = (ks & 3) * 2 + (lane >> 4);
            const int ar = wid * 16 + lr;
            const uint32_t aoff = ar * 128 + ((g ^ (ar & 7)) << 4);
            uint32_t ahi[4], alo[4];
            LDSM_X4(ahi, QS + chunk * 16384 + aoff);
            LDSM_X4(alo, QS + (2 + chunk) * 16384 + aoff);
#pragma unroll
            for (int np = 0; np < 8; np++) {
                const int br = np * 16 + lr;
                const uint32_t boff = br * 128 + ((g ^ (br & 7)) << 4);
                uint32_t t4[4], u4[4];
                LDSM_X4(t4, kst + chunk * 16384 + boff);
                LDSM_X4(u4, kst + (2 + chunk) * 16384 + boff);
                {
                    uint32_t b0[2] = { t4[0], t4[2] };
                    uint32_t c0_[2] = { u4[0], u4[2] };
                    mma16816_bf(sacc[2*np], ahi, b0);
                    mma16816_bf(sacc[2*np], ahi, c0_);
                    mma16816_bf(sacc[2*np], alo, b0);
                }
                {
                    uint32_t b1[2] = { t4[1], t4[3] };
                    uint32_t c1_[2] = { u4[1], u4[3] };
                    mma16816_bf(sacc[2*np+1], ahi, b1);
                    mma16816_bf(sacc[2*np+1], ahi, c1_);
                    mma16816_bf(sacc[2*np+1], alo, b1);
                }
            }
        }

        // ---- scale + causal mask (diagonal tile only) ----
        const bool diag = (j == qb);
        const int rg0 = wid * 16 + rloc;   // local row in [0,128)
#pragma unroll
        for (int nt = 0; nt < 16; nt++) {
            float* s = sacc[nt];
            s[0] *= scale; s[1] *= scale; s[2] *= scale; s[3] *= scale;
            if (diag) {
                const int cl = nt * 8 + colloc;
                if (cl     > rg0)     s[0] = -1e30f;
                if (cl + 1 > rg0)     s[1] = -1e30f;
                if (cl     > rg0 + 8) s[2] = -1e30f;
                if (cl + 1 > rg0 + 8) s[3] = -1e30f;
            }
        }

        // ---- online softmax (rows within 4-lane quad) ----
        float mx0 = -1e30f, mx1 = -1e30f;
#pragma unroll
        for (int nt = 0; nt < 16; nt++) {
            mx0 = fmaxf(mx0, fmaxf(sacc[nt][0], sacc[nt][1]));
            mx1 = fmaxf(mx1, fmaxf(sacc[nt][2], sacc[nt][3]));
        }
        mx0 = fmaxf(mx0, __shfl_xor_sync(0xffffffffu, mx0, 1));
        mx0 = fmaxf(mx0, __shfl_xor_sync(0xffffffffu, mx0, 2));
        mx1 = fmaxf(mx1, __shfl_xor_sync(0xffffffffu, mx1, 1));
        mx1 = fmaxf(mx1, __shfl_xor_sync(0xffffffffu, mx1, 2));
        const float mn0 = fmaxf(m0, mx0), mn1 = fmaxf(m1, mx1);
        const float cr0 = __expf(m0 - mn0), cr1 = __expf(m1 - mn1);
        l0 *= cr0; l1 *= cr1; m0 = mn0; m1 = mn1;
#pragma unroll
        for (int nt = 0; nt < 16; nt++) {
            oacc[nt][0] *= cr0; oacc[nt][1] *= cr0;
            oacc[nt][2] *= cr1; oacc[nt][3] *= cr1;
        }
        float ps0 = 0.f, ps1 = 0.f;
#pragma unroll
        for (int kb = 0; kb < 8; kb++) {
            const float p00 = __expf(sacc[2*kb][0]   - mn0), p01 = __expf(sacc[2*kb][1]   - mn0);
            const float p02 = __expf(sacc[2*kb][2]   - mn1), p03 = __expf(sacc[2*kb][3]   - mn1);
            const float p10 = __expf(sacc[2*kb+1][0] - mn0), p11 = __expf(sacc[2*kb+1][1] - mn0);
            const float p12 = __expf(sacc[2*kb+1][2] - mn1), p13 = __expf(sacc[2*kb+1][3] - mn1);
            pfrag[kb][0] = packh2(p00, p01);
            pfrag[kb][1] = packh2(p02, p03);
            pfrag[kb][2] = packh2(p10, p11);
            pfrag[kb][3] = packh2(p12, p13);
            ps0 += p00 + p01 + p10 + p11;
            ps1 += p02 + p03 + p12 + p13;
        }
        ps0 += __shfl_xor_sync(0xffffffffu, ps0, 1);
        ps0 += __shfl_xor_sync(0xffffffffu, ps0, 2);
        ps1 += __shfl_xor_sync(0xffffffffu, ps1, 1);
        ps1 += __shfl_xor_sync(0xffffffffu, ps1, 2);
        l0 += ps0; l1 += ps1;

        // prefetch next K under PV
        if (j + 1 < nkt) { loadK(j + 1, sK ^ 1); CP_COMMIT(); }

        // ---- O += P V  (fp16) ----
#pragma unroll
        for (int kb = 0; kb < 8; kb++) {
            const int chunk = kb >> 2;
            const int g = (kb & 3) * 2 + (lane >> 4);
#pragma unroll
            for (int np = 0; np < 8; np++) {
                const int br = np * 16 + lr;
                const uint32_t boff = br * 128 + ((g ^ (br & 7)) << 4);
                uint32_t t4[4];
                LDSM_X4(t4, VS + chunk * 16384 + boff);
                uint32_t b0[2] = { t4[0], t4[2] };
                uint32_t b1[2] = { t4[1], t4[3] };
                mma16816_fp(oacc[2*np],   pfrag[kb], b0);
                mma16816_fp(oacc[2*np+1], pfrag[kb], b1);
            }
        }
        __syncthreads();   // V consumed by all warps
        if (j + 1 < nkt) { loadV(j + 1); CP_COMMIT(); }
    }

    // ---- writeout: AO[b, t, h*128 + d] ----
    const float inv0 = 1.f / l0, inv1 = 1.f / l1;
    const int bb = bh >> 4, hh = bh & 15;
    const int rgg0 = qb * 128 + wid * 16 + rloc;
    float* base0 = g_AO + ((size_t)(bb * 2048 + rgg0)) * 2048 + hh * 128;
    float* base1 = base0 + (size_t)8 * 2048;
#pragma unroll
    for (int nt = 0; nt < 16; nt++) {
        const int d = nt * 8 + colloc;
        *(float2*)(base0 + d) = make_float2(oacc[nt][0] * inv0, oacc[nt][1] * inv0);
        *(float2*)(base1 + d) = make_float2(oacc[nt][2] * inv1, oacc[nt][3] * inv1);
    }
}

// ---------------- launch ----------------
extern "C" void kernel_launch(void* const* d_in, const int* in_sizes, int n_in,
                              void* d_out, int out_size)
{
    (void)in_sizes; (void)n_in; (void)out_size;
    const float* hidden = (const float*)d_in[0];
    const float* q_w = (const float*)d_in[2];
    const float* k_w = (const float*)d_in[3];
    const float* v_w = (const float*)d_in[4];
    const float* o_w = (const float*)d_in[5];
    float* out = (float*)d_out;

    cudaFuncSetAttribute(gemm_mma<0>, cudaFuncAttributeMaxDynamicSharedMemorySize, 131072);
    cudaFuncSetAttribute(gemm_mma<1>, cudaFuncAttributeMaxDynamicSharedMemorySize, 131072);
    cudaFuncSetAttribute(flash_mma, cudaFuncAttributeMaxDynamicSharedMemorySize, FL_SMEM);

    convert_all<<<dim3(8192, 5), 256>>>(hidden, q_w, k_w, v_w, o_w);
    gemm_mma<1><<<dim3(48, 32), 256, 131072>>>(nullptr);
    rope_kernel<<<32768, 256>>>();
    abar_cam<<<32, 256>>>();
    convert_vt<<<dim3(64, 32), 256>>>();
    flash_mma<<<dim3(16, 32), 256, FL_SMEM>>>();
    convert_ao<<<8192, 256>>>();
    gemm_mma<0><<<dim3(16, 32), 256, 131072>>>(out);
}

// round 10
// speedup vs baseline: 2.5304x; 1.0306x over previous
#include <cuda_runtime.h>
#include <cuda_bf16.h>
#include <cuda_fp16.h>
#include <math.h>
#include <stdint.h>
#include <float.h>

#define B_  2
#define T_  2048
#define HID_ 2048
#define H_  16
#define D_  128
#define BH_ (B_*H_)
#define BT_ (B_*T_)

// ---------------- device scratch ----------------
__device__ float g_V[(size_t)BH_ * T_ * D_];
__device__ float g_ve[BH_ * D_];

// bf16 split operands
__device__ __align__(16) __nv_bfloat16 g_Hh[(size_t)BT_ * HID_];
__device__ __align__(16) __nv_bfloat16 g_Hl[(size_t)BT_ * HID_];
__device__ __align__(16) __nv_bfloat16 g_Wh[3][(size_t)HID_ * HID_];
__device__ __align__(16) __nv_bfloat16 g_Wl[3][(size_t)HID_ * HID_];
__device__ __align__(16) __nv_bfloat16 g_OWh[(size_t)HID_ * HID_];
__device__ __align__(16) __nv_bfloat16 g_OWl[(size_t)HID_ * HID_];
__device__ __align__(16) __nv_bfloat16 g_AOh[(size_t)BT_ * HID_];
__device__ __align__(16) __nv_bfloat16 g_AOl[(size_t)BT_ * HID_];
__device__ __align__(16) __nv_bfloat16 g_Qh[(size_t)BH_ * T_ * D_];
__device__ __align__(16) __nv_bfloat16 g_Ql[(size_t)BH_ * T_ * D_];
__device__ __align__(16) __nv_bfloat16 g_Kh[(size_t)BH_ * T_ * D_];
__device__ __align__(16) __nv_bfloat16 g_Kl[(size_t)BH_ * T_ * D_];
// fp16 V transposed: Vt[bh][d][k]
__device__ __align__(16) __half g_Vth[(size_t)BH_ * D_ * T_];

// ---------------- PTX helpers (compute_103-safe) ----------------
__device__ __forceinline__ uint32_t smem_u32(const void* p) {
    uint32_t a;
    asm("{ .reg .u64 t; cvta.to.shared.u64 t, %1; cvt.u32.u64 %0, t; }" : "=r"(a) : "l"(p));
    return a;
}
__device__ __forceinline__ void cp_async16(uint32_t dst, const void* src) {
    asm volatile("cp.async.cg.shared.global [%0], [%1], 16;" :: "r"(dst), "l"(src));
}
#define CP_COMMIT() asm volatile("cp.async.commit_group;" ::: "memory")
#define CP_WAIT(N)  asm volatile("cp.async.wait_group %0;" :: "n"(N) : "memory")

#define LDSM_X4(r, addr) \
    asm volatile("ldmatrix.sync.aligned.m8n8.x4.shared.b16 {%0,%1,%2,%3}, [%4];" \
        : "=r"((r)[0]), "=r"((r)[1]), "=r"((r)[2]), "=r"((r)[3]) : "r"(addr))

__device__ __forceinline__ void mma16816_bf(float* c, const uint32_t* a, const uint32_t* b) {
    asm volatile("mma.sync.aligned.m16n8k16.row.col.f32.bf16.bf16.f32 "
        "{%0,%1,%2,%3}, {%4,%5,%6,%7}, {%8,%9}, {%0,%1,%2,%3};"
        : "+f"(c[0]), "+f"(c[1]), "+f"(c[2]), "+f"(c[3])
        : "r"(a[0]), "r"(a[1]), "r"(a[2]), "r"(a[3]), "r"(b[0]), "r"(b[1]));
}
__device__ __forceinline__ void mma16816_fp(float* c, const uint32_t* a, const uint32_t* b) {
    asm volatile("mma.sync.aligned.m16n8k16.row.col.f32.f16.f16.f32 "
        "{%0,%1,%2,%3}, {%4,%5,%6,%7}, {%8,%9}, {%0,%1,%2,%3};"
        : "+f"(c[0]), "+f"(c[1]), "+f"(c[2]), "+f"(c[3])
        : "r"(a[0]), "r"(a[1]), "r"(a[2]), "r"(a[3]), "r"(b[0]), "r"(b[1]));
}

__device__ __forceinline__ void split2(float x, __nv_bfloat16& h, __nv_bfloat16& l) {
    h = __float2bfloat16(x);
    l = __float2bfloat16(x - __bfloat162float(h));
}
__device__ __forceinline__ uint32_t packh2(float a, float b) {
    __half2 h = __floats2half2_rn(a, b);
    return *reinterpret_cast<uint32_t*>(&h);
}

// ---------------- merged fp32 -> bf16 hi/lo split for inputs ----------------
__global__ void convert_all(const float* __restrict__ hs,
                            const float* __restrict__ qw, const float* __restrict__ kw,
                            const float* __restrict__ vw, const float* __restrict__ ow)
{
    const int sel = blockIdx.y;
    if (sel > 0 && blockIdx.x >= 4096) return;
    const size_t i = ((size_t)blockIdx.x * blockDim.x + threadIdx.x) * 4;
    const float* s;
    __nv_bfloat16 *hi, *lo;
    switch (sel) {
        case 0: s = hs; hi = g_Hh;    lo = g_Hl;    break;
        case 1: s = qw; hi = g_Wh[0]; lo = g_Wl[0]; break;
        case 2: s = kw; hi = g_Wh[1]; lo = g_Wl[1]; break;
        case 3: s = vw; hi = g_Wh[2]; lo = g_Wl[2]; break;
        default: s = ow; hi = g_OWh;  lo = g_OWl;   break;
    }
    const float4 v = *(const float4*)(s + i);
    __nv_bfloat16 h0,h1,h2,h3,l0,l1,l2,l3;
    split2(v.x,h0,l0); split2(v.y,h1,l1); split2(v.z,h2,l2); split2(v.w,h3,l3);
    *(__nv_bfloat162*)(hi + i)     = __nv_bfloat162(h0, h1);
    *(__nv_bfloat162*)(hi + i + 2) = __nv_bfloat162(h2, h3);
    *(__nv_bfloat162*)(lo + i)     = __nv_bfloat162(l0, l1);
    *(__nv_bfloat162*)(lo + i + 2) = __nv_bfloat162(l2, l3);
}

// ---------------- mma.sync split-bf16 GEMM (projections), 3-stage pipeline ----------------
// MODE 1: QKV proj grid(48,32): x=(w*16+n). Q/K: rope fused in epilogue -> bf16 splits.
//         V: fp32 -> g_V [b,h,t,d].
// MODE 0: O proj   grid(16,32) -> C (d_out)
#define GT_TILE  16384
#define GT_STAGE (4 * GT_TILE)     // 64KB per stage (Ah,Al,Bh,Bl)
#define GT_SMEM  (3 * GT_STAGE)    // 192KB, 3 stages

template<int MODE>
__global__ void __launch_bounds__(256) gemm_mma(float* __restrict__ C)
{
    extern __shared__ char smem[];
    const uint32_t sbase = smem_u32(smem);
    const int tid = threadIdx.x;
    const int wid = tid >> 5;
    const int lane = tid & 31;

    int wsel = 0, hsel = 0, mloc, nloc;
    const __nv_bfloat16 *pA0, *pA1, *pB0, *pB1;
    if (MODE == 1) {
        wsel = blockIdx.x >> 4;
        hsel = blockIdx.x & 15;
        mloc = blockIdx.y * 128; nloc = hsel * 128;
        pA0 = g_Hh; pA1 = g_Hl; pB0 = g_Wh[wsel]; pB1 = g_Wl[wsel];
    } else {
        mloc = blockIdx.y * 128; nloc = blockIdx.x * 128;
        pA0 = g_AOh; pA1 = g_AOl; pB0 = g_OWh; pB1 = g_OWl;
    }

    const int part = tid >> 6;
    const int u = tid & 63;
    const __nv_bfloat16* gsrc = (part == 0) ? pA0 : (part == 1) ? pA1 : (part == 2) ? pB0 : pB1;
    const int growbase = (part < 2) ? mloc : nloc;
    const uint32_t tpart = sbase + part * GT_TILE;

    auto load_stage = [&](int c, int s) {
#pragma unroll
        for (int rr = 0; rr < 2; rr++) {
            const int r = u * 2 + rr;
            const __nv_bfloat16* src = gsrc + (size_t)(growbase + r) * 2048 + c * 64;
            const uint32_t drow = tpart + s * GT_STAGE + r * 128;
#pragma unroll
            for (int g = 0; g < 8; g++)
                cp_async16(drow + (((g ^ (r & 7)) << 4)), src + g * 8);
        }
    };

    const int wm = wid & 3;
    const int wn = wid >> 2;

    float acc[2][8][4];
#pragma unroll
    for (int a = 0; a < 2; a++)
#pragma unroll
        for (int b = 0; b < 8; b++)
#pragma unroll
            for (int cx = 0; cx < 4; cx++) acc[a][b][cx] = 0.f;

    load_stage(0, 0); CP_COMMIT();
    load_stage(1, 1); CP_COMMIT();

    for (int c = 0; c < 32; ++c) {
        if (c < 31) { CP_WAIT(1); } else { CP_WAIT(0); }
        __syncthreads();

        const uint32_t st = sbase + (c % 3) * GT_STAGE;
#pragma unroll
        for (int ks = 0; ks < 4; ks++) {
            const int lr = lane & 15;
            const int g = ks * 2 + (lane >> 4);

            uint32_t ah[2][4], al[2][4];
#pragma unroll
            for (int mb = 0; mb < 2; mb++) {
                const int r = wm * 32 + mb * 16 + lr;
                const uint32_t off = r * 128 + (((g ^ (r & 7)) << 4));
                LDSM_X4(ah[mb], st + off);
                LDSM_X4(al[mb], st + GT_TILE + off);
            }
            uint32_t bhf[8][2], blf[8][2];
#pragma unroll
            for (int np = 0; np < 4; np++) {
                const int r = wn * 64 + np * 16 + lr;
                const uint32_t off = r * 128 + (((g ^ (r & 7)) << 4));
                uint32_t t4[4];
                LDSM_X4(t4, st + 2 * GT_TILE + off);
                bhf[2*np][0] = t4[0]; bhf[2*np][1] = t4[2];
                bhf[2*np+1][0] = t4[1]; bhf[2*np+1][1] = t4[3];
                LDSM_X4(t4, st + 3 * GT_TILE + off);
                blf[2*np][0] = t4[0]; blf[2*np][1] = t4[2];
                blf[2*np+1][0] = t4[1]; blf[2*np+1][1] = t4[3];
            }
#pragma unroll
            for (int mb = 0; mb < 2; mb++)
#pragma unroll
                for (int nb = 0; nb < 8; nb++) {
                    mma16816_bf(acc[mb][nb], ah[mb], bhf[nb]);
                    mma16816_bf(acc[mb][nb], ah[mb], blf[nb]);
                    mma16816_bf(acc[mb][nb], al[mb], bhf[nb]);
                }
        }
        if (c + 2 < 32) { load_stage(c + 2, (c + 2) % 3); CP_COMMIT(); }
    }

    // ---------------- epilogue ----------------
    if (MODE == 0) {
#pragma unroll
        for (int mb = 0; mb < 2; mb++)
#pragma unroll
            for (int rh = 0; rh < 2; rh++) {
                const int row = wm * 32 + mb * 16 + rh * 8 + (lane >> 2);
                float* dst = C + (size_t)(mloc + row) * 2048 + nloc;
                const int cbase = wn * 64 + (lane & 3) * 2;
#pragma unroll
                for (int nb = 0; nb < 8; nb++)
                    *(float2*)(dst + cbase + nb * 8) =
                        make_float2(acc[mb][nb][rh * 2], acc[mb][nb][rh * 2 + 1]);
            }
    } else if (wsel == 2) {
        // V: fp32 to g_V [b,h,t,d]
#pragma unroll
        for (int mb = 0; mb < 2; mb++)
#pragma unroll
            for (int rh = 0; rh < 2; rh++) {
                const int gr = mloc + wm * 32 + mb * 16 + rh * 8 + (lane >> 2);
                const int bb = gr >> 11, t = gr & 2047;
                float* dst = g_V + (((size_t)(bb * H_ + hsel) * T_ + t) << 7);
                const int cbase = wn * 64 + (lane & 3) * 2;
#pragma unroll
                for (int nb = 0; nb < 8; nb++)
                    *(float2*)(dst + cbase + nb * 8) =
                        make_float2(acc[mb][nb][rh * 2], acc[mb][nb][rh * 2 + 1]);
            }
    } else {
        // Q/K: stage to smem, apply RoPE, emit bf16 hi/lo splits
        __syncthreads();
        float* stg = (float*)smem;     // [128][132]
#pragma unroll
        for (int mb = 0; mb < 2; mb++)
#pragma unroll
            for (int rh = 0; rh < 2; rh++) {
                const int row = wm * 32 + mb * 16 + rh * 8 + (lane >> 2);
                const int cbase = wn * 64 + (lane & 3) * 2;
#pragma unroll
                for (int nb = 0; nb < 8; nb++) {
                    stg[row * 132 + cbase + nb * 8]     = acc[mb][nb][rh * 2];
                    stg[row * 132 + cbase + nb * 8 + 1] = acc[mb][nb][rh * 2 + 1];
                }
            }
        __syncthreads();

        __nv_bfloat16* Oh = (wsel == 0) ? g_Qh : g_Kh;
        __nv_bfloat16* Ol = (wsel == 0) ? g_Ql : g_Kl;
        for (int idx = tid; idx < 128 * 64; idx += 256) {
            const int r = idx >> 6, j = idx & 63;
            const int gr = mloc + r;
            const int bb = gr >> 11, t = gr & 2047;
            const float inv = powf(10000.f, -(float)j * (1.f / 64.f));
            float s, cc;
            sincosf((float)t * inv, &s, &cc);
            const float x1 = stg[r * 132 + j];
            const float x2 = stg[r * 132 + j + 64];
            const float y1 = x1 * cc - x2 * s;
            const float y2 = x2 * cc + x1 * s;
            const size_t base = (((size_t)(bb * H_ + hsel) * T_ + t) << 7);
            __nv_bfloat16 h, l;
            split2(y1, h, l); Oh[base + j] = h;      Ol[base + j] = l;
            split2(y2, h, l); Oh[base + j + 64] = h; Ol[base + j + 64] = l;
        }
    }
}

// ---------------- A_bar softmax + CAM bernoulli -> g_ve (reads bf16 splits) ----------------
__device__ __forceinline__ uint32_t rotl32(uint32_t x, int r) { return (x << r) | (x >> (32 - r)); }

__global__ void __launch_bounds__(256) abar_cam()
{
    const int bh = blockIdx.x;
    __shared__ float qrow[128];
    __shared__ float sc[2048];
    __shared__ float red[256];
    __shared__ float maskf;
    const int tid = threadIdx.x;

    const size_t qoff = ((size_t)bh * T_ + (T_ - 1)) * 128;
    if (tid < 128)
        qrow[tid] = __bfloat162float(g_Qh[qoff + tid]) + __bfloat162float(g_Ql[qoff + tid]);
    __syncthreads();

    for (int k = tid; k < 2048; k += 256) {
        const size_t koff = ((size_t)bh * T_ + k) * 128;
        const __nv_bfloat162* kh = (const __nv_bfloat162*)(g_Kh + koff);
        const __nv_bfloat162* kl = (const __nv_bfloat162*)(g_Kl + koff);
        float s = 0.f;
#pragma unroll
        for (int i = 0; i < 64; i++) {
            const __nv_bfloat162 a = kh[i], b = kl[i];
            const float kx = __bfloat162float(a.x) + __bfloat162float(b.x);
            const float ky = __bfloat162float(a.y) + __bfloat162float(b.y);
            s = fmaf(kx, qrow[2 * i], s);
            s = fmaf(ky, qrow[2 * i + 1], s);
        }
        sc[k] = s * 0.08838834764831845f;
    }
    __syncthreads();

    float m = -FLT_MAX;
    for (int k = tid; k < 2048; k += 256) m = fmaxf(m, sc[k]);
    red[tid] = m; __syncthreads();
    for (int o = 128; o > 0; o >>= 1) { if (tid < o) red[tid] = fmaxf(red[tid], red[tid + o]); __syncthreads(); }
    const float gm = red[0];
    __syncthreads();

    float sum = 0.f;
    for (int k = tid; k < 2048; k += 256) { const float p = expf(sc[k] - gm); sc[k] = p; sum += p; }
    red[tid] = sum; __syncthreads();
    for (int o = 128; o > 0; o >>= 1) { if (tid < o) red[tid] += red[tid + o]; __syncthreads(); }
    const float invs = 1.f / red[0];
    __syncthreads();

    for (int k = tid; k < 2048; k += 256) sc[k] *= invs;
    __syncthreads();

    float ws = 0.f;
    for (int k = 1536 + tid; k < 2048; k += 256) ws += sc[k];
    red[tid] = ws; __syncthreads();
    for (int o = 128; o > 0; o >>= 1) { if (tid < o) red[tid] += red[tid + o]; __syncthreads(); }

    if (tid == 0) {
        const float avg = fmaxf(red[0] * (1.f / 512.f), 1e-6f);
        float p = fminf(fmaxf(sc[1535] / avg, 0.f), 1.f);
        uint32_t x0 = 0u, x1 = (uint32_t)bh;
        const uint32_t k0 = 0u, k1 = 42u, k2 = 0x1BD11BDAu ^ k0 ^ k1;
        x0 += k0; x1 += k1;
#define TF4(a,b,c,d)  x0+=x1; x1=rotl32(x1,a); x1^=x0; \
                      x0+=x1; x1=rotl32(x1,b); x1^=x0; \
                      x0+=x1; x1=rotl32(x1,c); x1^=x0; \
                      x0+=x1; x1=rotl32(x1,d); x1^=x0;
        TF4(13,15,26,6)   x0 += k1; x1 += k2 + 1u;
        TF4(17,29,16,24)  x0 += k2; x1 += k0 + 2u;
        TF4(13,15,26,6)   x0 += k0; x1 += k1 + 3u;
        TF4(17,29,16,24)  x0 += k1; x1 += k2 + 4u;
        TF4(13,15,26,6)   x0 += k2; x1 += k0 + 5u;
#undef TF4
        const uint32_t bits = x0 ^ x1;
        float uu = __uint_as_float((bits >> 9) | 0x3f800000u) - 1.0f;
        uu = fmaxf(uu, 0.f);
        maskf = (uu < p) ? 1.f : 0.f;
    }
    __syncthreads();

    if (tid < 128)
        g_ve[bh * 128 + tid] = g_V[((size_t)bh * T_ + 1535) * 128 + tid] * maskf * (1.f / 512.f);
}

// V -> transposed fp16 Vt[bh][d][k], fused CAM window update (+v_e for k>=1536)
__global__ void __launch_bounds__(256) convert_vt()
{
    __shared__ float tile[64][65];
    const int bh = blockIdx.y;
    const int kt = blockIdx.x >> 1;
    const int dt = blockIdx.x & 1;
    const int k0 = kt * 64, d0 = dt * 64;
    const int tid = threadIdx.x;

    for (int idx = tid; idx < 64 * 64; idx += 256) {
        const int i = idx >> 6, j = idx & 63;
        tile[i][j] = g_V[((size_t)bh * T_ + k0 + i) * 128 + d0 + j];
    }
    __syncthreads();
    for (int idx = tid; idx < 64 * 64; idx += 256) {
        const int j = idx >> 6, i = idx & 63;
        float x = tile[i][j];
        if (k0 + i >= 1536) x += g_ve[bh * 128 + d0 + j];
        g_Vth[((size_t)bh * D_ + d0 + j) * T_ + k0 + i] = __float2half_rn(x);
    }
}

// ---------------- fused flash attention (mma) ----------------
#define FL_SMEM 229376

__global__ void __launch_bounds__(256) flash_mma()
{
    extern __shared__ char smem[];
    const uint32_t sb = smem_u32(smem);
    const uint32_t QS = sb, KS = sb + 65536, VS = sb + 196608;
    const int tid = threadIdx.x, wid = tid >> 5, lane = tid & 31;
    const int bh = blockIdx.y;
    const int qb = 15 - blockIdx.x;
    const int nkt = qb + 1;

    {
        const int part = tid >> 6, u = tid & 63;
        const int plane = part >> 1, c = part & 1;
        const __nv_bfloat16* base = (plane ? g_Ql : g_Qh) + ((size_t)(bh * 2048 + qb * 128)) * 128 + c * 64;
        const uint32_t dstt = QS + part * 16384;
#pragma unroll
        for (int rr = 0; rr < 2; rr++) {
            const int r = u * 2 + rr;
            const char* sp = (const char*)(base + (size_t)r * 128);
            const uint32_t drow = dstt + r * 128;
#pragma unroll
            for (int g = 0; g < 8; g++) cp_async16(drow + ((g ^ (r & 7)) << 4), sp + g * 16);
        }
    }
    CP_COMMIT();

    auto loadK = [&](int j, int s) {
        const int part = tid >> 6, u = tid & 63;
        const int plane = part >> 1, c = part & 1;
        const __nv_bfloat16* base = (plane ? g_Kl : g_Kh) + ((size_t)(bh * 2048 + j * 128)) * 128 + c * 64;
        const uint32_t dstt = KS + s * 65536 + part * 16384;
#pragma unroll
        for (int rr = 0; rr < 2; rr++) {
            const int r = u * 2 + rr;
            const char* sp = (const char*)(base + (size_t)r * 128);
            const uint32_t drow = dstt + r * 128;
#pragma unroll
            for (int g = 0; g < 8; g++) cp_async16(drow + ((g ^ (r & 7)) << 4), sp + g * 16);
        }
    };
    auto loadV = [&](int j) {
        const int c = tid >> 7, r = tid & 127;
        const char* sp = (const char*)(g_Vth + ((size_t)(bh * 128 + r)) * 2048 + j * 128 + c * 64);
        const uint32_t drow = VS + c * 16384 + r * 128;
#pragma unroll
        for (int g = 0; g < 8; g++) cp_async16(drow + ((g ^ (r & 7)) << 4), sp + g * 16);
    };

    loadK(0, 0); CP_COMMIT();
    loadV(0);    CP_COMMIT();

    float oacc[16][4];
#pragma unroll
    for (int nt = 0; nt < 16; nt++)
#pragma unroll
        for (int e = 0; e < 4; e++) oacc[nt][e] = 0.f;
    float m0 = -1e30f, m1 = -1e30f, l0 = 0.f, l1 = 0.f;
    uint32_t pfrag[8][4];

    const float scale = 0.08838834764831845f;
    const int lr = lane & 15;
    const int rloc = (lane >> 2);
    const int colloc = (lane & 3) * 2;

    for (int j = 0; j < nkt; j++) {
        const int sK = j & 1;
        CP_WAIT(0);
        __syncthreads();

        float sacc[16][4];
#pragma unroll
        for (int nt = 0; nt < 16; nt++)
#pragma unroll
            for (int e = 0; e < 4; e++) sacc[nt][e] = 0.f;

        const uint32_t kst = KS + sK * 65536;
#pragma unroll
        for (int ks = 0; ks < 8; ks++) {
            const int chunk = ks >> 2;
            const int g = (ks & 3) * 2 + (lane >> 4);
            const int ar = wid * 16 + lr;
            const uint32_t aoff = ar * 128 + ((g ^ (ar & 7)) << 4);
            uint32_t ahi[4], alo[4];
            LDSM_X4(ahi, QS + chunk * 16384 + aoff);
            LDSM_X4(alo, QS + (2 + chunk) * 16384 + aoff);
#pragma unroll
            for (int np = 0; np < 8; np++) {
                const int br = np * 16 + lr;
                const uint32_t boff = br * 128 + ((g ^ (br & 7)) << 4);
                uint32_t t4[4], u4[4];
                LDSM_X4(t4, kst + chunk * 16384 + boff);
                LDSM_X4(u4, kst + (2 + chunk) * 16384 + boff);
                {
                    uint32_t b0[2] = { t4[0], t4[2] };
                    uint32_t c0_[2] = { u4[0], u4[2] };
                    mma16816_bf(sacc[2*np], ahi, b0);
                    mma16816_bf(sacc[2*np], ahi, c0_);
                    mma16816_bf(sacc[2*np], alo, b0);
                }
                {
                    uint32_t b1[2] = { t4[1], t4[3] };
                    uint32_t c1_[2] = { u4[1], u4[3] };
                    mma16816_bf(sacc[2*np+1], ahi, b1);
                    mma16816_bf(sacc[2*np+1], ahi, c1_);
                    mma16816_bf(sacc[2*np+1], alo, b1);
                }
            }
        }

        const bool diag = (j == qb);
        const int rg0 = wid * 16 + rloc;
#pragma unroll
        for (int nt = 0; nt < 16; nt++) {
            float* s = sacc[nt];
            s[0] *= scale; s[1] *= scale; s[2] *= scale; s[3] *= scale;
            if (diag) {
                const int cl = nt * 8 + colloc;
                if (cl     > rg0)     s[0] = -1e30f;
                if (cl + 1 > rg0)     s[1] = -1e30f;
                if (cl     > rg0 + 8) s[2] = -1e30f;
                if (cl + 1 > rg0 + 8) s[3] = -1e30f;
            }
        }

        float mx0 = -1e30f, mx1 = -1e30f;
#pragma unroll
        for (int nt = 0; nt < 16; nt++) {
            mx0 = fmaxf(mx0, fmaxf(sacc[nt][0], sacc[nt][1]));
            mx1 = fmaxf(mx1, fmaxf(sacc[nt][2], sacc[nt][3]));
        }
        mx0 = fmaxf(mx0, __shfl_xor_sync(0xffffffffu, mx0, 1));
        mx0 = fmaxf(mx0, __shfl_xor_sync(0xffffffffu, mx0, 2));
        mx1 = fmaxf(mx1, __shfl_xor_sync(0xffffffffu, mx1, 1));
        mx1 = fmaxf(mx1, __shfl_xor_sync(0xffffffffu, mx1, 2));
        const float mn0 = fmaxf(m0, mx0), mn1 = fmaxf(m1, mx1);
        const float cr0 = __expf(m0 - mn0), cr1 = __expf(m1 - mn1);
        l0 *= cr0; l1 *= cr1; m0 = mn0; m1 = mn1;
#pragma unroll
        for (int nt = 0; nt < 16; nt++) {
            oacc[nt][0] *= cr0; oacc[nt][1] *= cr0;
            oacc[nt][2] *= cr1; oacc[nt][3] *= cr1;
        }
        float ps0 = 0.f, ps1 = 0.f;
#pragma unroll
        for (int kb = 0; kb < 8; kb++) {
            const float p00 = __expf(sacc[2*kb][0]   - mn0), p01 = __expf(sacc[2*kb][1]   - mn0);
            const float p02 = __expf(sacc[2*kb][2]   - mn1), p03 = __expf(sacc[2*kb][3]   - mn1);
            const float p10 = __expf(sacc[2*kb+1][0] - mn0), p11 = __expf(sacc[2*kb+1][1] - mn0);
            const float p12 = __expf(sacc[2*kb+1][2] - mn1), p13 = __expf(sacc[2*kb+1][3] - mn1);
            pfrag[kb][0] = packh2(p00, p01);
            pfrag[kb][1] = packh2(p02, p03);
            pfrag[kb][2] = packh2(p10, p11);
            pfrag[kb][3] = packh2(p12, p13);
            ps0 += p00 + p01 + p10 + p11;
            ps1 += p02 + p03 + p12 + p13;
        }
        ps0 += __shfl_xor_sync(0xffffffffu, ps0, 1);
        ps0 += __shfl_xor_sync(0xffffffffu, ps0, 2);
        ps1 += __shfl_xor_sync(0xffffffffu, ps1, 1);
        ps1 += __shfl_xor_sync(0xffffffffu, ps1, 2);
        l0 += ps0; l1 += ps1;

        if (j + 1 < nkt) { loadK(j + 1, sK ^ 1); CP_COMMIT(); }

#pragma unroll
        for (int kb = 0; kb < 8; kb++) {
            const int chunk = kb >> 2;
            const int g = (kb & 3) * 2 + (lane >> 4);
#pragma unroll
            for (int np = 0; np < 8; np++) {
                const int br = np * 16 + lr;
                const uint32_t boff = br * 128 + ((g ^ (br & 7)) << 4);
                uint32_t t4[4];
                LDSM_X4(t4, VS + chunk * 16384 + boff);
                uint32_t b0[2] = { t4[0], t4[2] };
                uint32_t b1[2] = { t4[1], t4[3] };
                mma16816_fp(oacc[2*np],   pfrag[kb], b0);
                mma16816_fp(oacc[2*np+1], pfrag[kb], b1);
            }
        }
        __syncthreads();
        if (j + 1 < nkt) { loadV(j + 1); CP_COMMIT(); }
    }

    // ---- writeout: bf16 hi/lo splits of AO ----
    const float inv0 = 1.f / l0, inv1 = 1.f / l1;
    const int bb = bh >> 4, hh = bh & 15;
    const int rgg0 = qb * 128 + wid * 16 + rloc;
    const size_t base0 = ((size_t)(bb * 2048 + rgg0)) * 2048 + hh * 128;
    const size_t base1 = base0 + (size_t)8 * 2048;
#pragma unroll
    for (int nt = 0; nt < 16; nt++) {
        const int d = nt * 8 + colloc;
        __nv_bfloat16 h0, l0_, h1, l1_;
        split2(oacc[nt][0] * inv0, h0, l0_);
        split2(oacc[nt][1] * inv0, h1, l1_);
        *(__nv_bfloat162*)(g_AOh + base0 + d) = __nv_bfloat162(h0, h1);
        *(__nv_bfloat162*)(g_AOl + base0 + d) = __nv_bfloat162(l0_, l1_);
        split2(oacc[nt][2] * inv1, h0, l0_);
        split2(oacc[nt][3] * inv1, h1, l1_);
        *(__nv_bfloat162*)(g_AOh + base1 + d) = __nv_bfloat162(h0, h1);
        *(__nv_bfloat162*)(g_AOl + base1 + d) = __nv_bfloat162(l0_, l1_);
    }
}

// ---------------- launch ----------------
extern "C" void kernel_launch(void* const* d_in, const int* in_sizes, int n_in,
                              void* d_out, int out_size)
{
    (void)in_sizes; (void)n_in; (void)out_size;
    const float* hidden = (const float*)d_in[0];
    const float* q_w = (const float*)d_in[2];
    const float* k_w = (const float*)d_in[3];
    const float* v_w = (const float*)d_in[4];
    const float* o_w = (const float*)d_in[5];
    float* out = (float*)d_out;

    cudaFuncSetAttribute(gemm_mma<0>, cudaFuncAttributeMaxDynamicSharedMemorySize, GT_SMEM);
    cudaFuncSetAttribute(gemm_mma<1>, cudaFuncAttributeMaxDynamicSharedMemorySize, GT_SMEM);
    cudaFuncSetAttribute(flash_mma, cudaFuncAttributeMaxDynamicSharedMemorySize, FL_SMEM);

    convert_all<<<dim3(8192, 5), 256>>>(hidden, q_w, k_w, v_w, o_w);
    gemm_mma<1><<<dim3(48, 32), 256, GT_SMEM>>>(nullptr);
    abar_cam<<<32, 256>>>();
    convert_vt<<<dim3(64, 32), 256>>>();
    flash_mma<<<dim3(16, 32), 256, FL_SMEM>>>();
    gemm_mma<0><<<dim3(16, 32), 256, GT_SMEM>>>(out);
}